// round 5
// baseline (speedup 1.0000x reference)
#include <cuda_runtime.h>
#include <cstdint>
#include <cstddef>

#define N_NODES 50000
#define N_EDGES 1600000
#define N_EI    (N_EDGES + N_NODES)
#define VOCAB   5000
#define HID     64
#define HEADS   4
#define NG      128
#define NCLS    20
#define NEG_SLOPE 0.2f

// ---------------- scratch (static device globals; no allocation) ----------------
__device__ float g_h1pre[N_NODES * HID];    // x @ W1
__device__ float g_al1s[N_NODES * HEADS];
__device__ float g_al1d[N_NODES * HEADS];
__device__ float g_acc1[N_NODES * HID];     // layer-1 weighted sum accumulator
__device__ float g_den1[N_NODES * HEADS];   // layer-1 softmax denominators
__device__ float g_h[N_NODES * HID];        // layer-1 output (post ELU)
__device__ float g_h2[N_NODES * HID];       // h @ W2
__device__ float g_al2s[N_NODES];
__device__ float g_al2d[N_NODES];
__device__ float g_acc2[N_NODES * HID];
__device__ float g_den2[N_NODES];
__device__ float g_pool[NG * HID];
__device__ float g_cnt[NG];

// ---------------- helpers ----------------
__device__ __forceinline__ void red_add_v4(float* p, float a, float b, float c, float d) {
    asm volatile("red.global.add.v4.f32 [%0], {%1, %2, %3, %4};"
                 :: "l"(p), "f"(a), "f"(b), "f"(c), "f"(d) : "memory");
}
__device__ __forceinline__ void red_add_f(float* p, float v) {
    asm volatile("red.global.add.f32 [%0], %1;" :: "l"(p), "f"(v) : "memory");
}

// ---------------- K0: zero all accumulators ----------------
__global__ void k_zero() {
    int i = blockIdx.x * blockDim.x + threadIdx.x;   // 800000 threads
    float4 z = make_float4(0.f, 0.f, 0.f, 0.f);
    if (i < N_NODES * HID / 4) {
        reinterpret_cast<float4*>(g_acc1)[i] = z;
        reinterpret_cast<float4*>(g_acc2)[i] = z;
    }
    if (i < N_NODES * HEADS / 4) reinterpret_cast<float4*>(g_den1)[i] = z;
    if (i < N_NODES / 4)         reinterpret_cast<float4*>(g_den2)[i] = z;
    if (i < NG * HID / 4)        reinterpret_cast<float4*>(g_pool)[i] = z;
    if (i < NG / 4)              reinterpret_cast<float4*>(g_cnt)[i]  = z;
}

// ---------------- K1: GEMM1  h1 = x[50000,5000] @ W1[5000,64] (fp32 SIMT) ----------------
#define BM 64
#define BN 64
#define BK 40   // 5000 = 125 * 40

__global__ __launch_bounds__(256) void k_gemm1(const float* __restrict__ A,
                                               const float* __restrict__ B) {
    __shared__ float As[BK][BM + 4];   // transposed tile; row stride 68 floats (16B aligned)
    __shared__ float Bs[BK][BN];

    int tid = threadIdx.x;
    int tx = tid & 15;          // output col group (4 cols)
    int ty = tid >> 4;          // output row group (4 rows)
    int m0 = blockIdx.x * BM;

    float acc[4][4];
#pragma unroll
    for (int i = 0; i < 4; i++)
#pragma unroll
        for (int j = 0; j < 4; j++) acc[i][j] = 0.f;

    for (int kt = 0; kt < VOCAB; kt += BK) {
        // load A tile: 64 rows x 40 cols = 640 float4
#pragma unroll
        for (int it = 0; it < 3; ++it) {
            int f = tid + it * 256;
            if (f < (BM * BK / 4)) {
                int m = f / (BK / 4);
                int kq = f % (BK / 4);
                int mg = m0 + m;
                float4 v = make_float4(0.f, 0.f, 0.f, 0.f);
                if (mg < N_NODES)
                    v = *reinterpret_cast<const float4*>(&A[(size_t)mg * VOCAB + kt + kq * 4]);
                As[kq * 4 + 0][m] = v.x;
                As[kq * 4 + 1][m] = v.y;
                As[kq * 4 + 2][m] = v.z;
                As[kq * 4 + 3][m] = v.w;
            }
        }
        // load B tile: 40 rows x 64 cols = 640 float4
#pragma unroll
        for (int it = 0; it < 3; ++it) {
            int f = tid + it * 256;
            if (f < (BK * BN / 4)) {
                int kk = f / (BN / 4);
                int nq = f % (BN / 4);
                *reinterpret_cast<float4*>(&Bs[kk][nq * 4]) =
                    *reinterpret_cast<const float4*>(&B[(size_t)(kt + kk) * HID + nq * 4]);
            }
        }
        __syncthreads();
#pragma unroll
        for (int kk = 0; kk < BK; ++kk) {
            float4 a4 = *reinterpret_cast<const float4*>(&As[kk][ty * 4]);
            float4 b4 = *reinterpret_cast<const float4*>(&Bs[kk][tx * 4]);
            float av[4] = {a4.x, a4.y, a4.z, a4.w};
            float bv[4] = {b4.x, b4.y, b4.z, b4.w};
#pragma unroll
            for (int i = 0; i < 4; i++)
#pragma unroll
                for (int j = 0; j < 4; j++) acc[i][j] += av[i] * bv[j];
        }
        __syncthreads();
    }
#pragma unroll
    for (int i = 0; i < 4; i++) {
        int mg = m0 + ty * 4 + i;
        if (mg < N_NODES)
            *reinterpret_cast<float4*>(&g_h1pre[(size_t)mg * HID + tx * 4]) =
                make_float4(acc[i][0], acc[i][1], acc[i][2], acc[i][3]);
    }
}

// ---------------- K2: per-node attention logits, layer 1 ----------------
__global__ void k_prep1(const float* __restrict__ a_src1, const float* __restrict__ a_dst1) {
    __shared__ float as[HID], ad[HID];
    if (threadIdx.x < HID) { as[threadIdx.x] = a_src1[threadIdx.x]; ad[threadIdx.x] = a_dst1[threadIdx.x]; }
    __syncthreads();
    int t = blockIdx.x * blockDim.x + threadIdx.x;
    int n = t >> 2, p = t & 3;       // p = head
    if (n >= N_NODES) return;
    const float4* hp = reinterpret_cast<const float4*>(&g_h1pre[n * HID + p * 16]);
    float s = 0.f, d = 0.f;
#pragma unroll
    for (int q = 0; q < 4; ++q) {
        float4 v = hp[q];
        int b = p * 16 + q * 4;
        s += v.x * as[b] + v.y * as[b + 1] + v.z * as[b + 2] + v.w * as[b + 3];
        d += v.x * ad[b] + v.y * ad[b + 1] + v.z * ad[b + 2] + v.w * ad[b + 3];
    }
    g_al1s[n * HEADS + p] = s;
    g_al1d[n * HEADS + p] = d;
}

// ---------------- K3: edge pass, layer 1 (16 threads / edge) ----------------
__global__ void k_edge1(const int* __restrict__ src, const int* __restrict__ dst) {
    int t = blockIdx.x * blockDim.x + threadIdx.x;
    int e = t >> 4;
    if (e >= N_EI) return;
    int l = t & 15;
    int s, d;
    if (e < N_EDGES) { s = src[e]; d = dst[e]; }
    else             { s = d = e - N_EDGES; }        // self loops
    int head = l >> 2;
    float al = g_al1s[s * HEADS + head] + g_al1d[d * HEADS + head];
    float ee = al > 0.f ? al : NEG_SLOPE * al;
    float w = __expf(ee);
    float4 hv = *reinterpret_cast<const float4*>(&g_h1pre[s * HID + l * 4]);
    red_add_v4(&g_acc1[d * HID + l * 4], hv.x * w, hv.y * w, hv.z * w, hv.w * w);
    if ((l & 3) == 0) red_add_f(&g_den1[d * HEADS + head], w);
}

// ---------------- K4: finish layer 1 (normalize + bias + ELU) ----------------
__global__ void k_fin1(const float* __restrict__ b1) {
    int i = blockIdx.x * blockDim.x + threadIdx.x;
    if (i >= N_NODES * HID) return;
    int n = i >> 6, c = i & 63;
    float v = g_acc1[i] / (g_den1[(n << 2) + (c >> 4)] + 1e-16f) + b1[c];
    g_h[i] = v > 0.f ? v : expm1f(v);
}

// ---------------- K5: GEMM2 (h @ W2) + layer-2 attention logits ----------------
__global__ __launch_bounds__(256) void k_layer2_mm(const float* __restrict__ W2,
                                                   const float* __restrict__ as2,
                                                   const float* __restrict__ ad2) {
    __shared__ float hs[4][HID];
    __shared__ float sred_s[8], sred_d[8];
    int tid = threadIdx.x;
    int c = tid & 63;
    int j = tid >> 6;  // node lane 0..3
    float wreg[HID];
#pragma unroll
    for (int k = 0; k < HID; ++k) wreg[k] = W2[k * HID + c];
    float asc = as2[c], adc = ad2[c];

    for (int n0 = blockIdx.x * 4; n0 < N_NODES; n0 += gridDim.x * 4) {
        int n = n0 + j;
        hs[j][c] = (n < N_NODES) ? g_h[(size_t)n * HID + c] : 0.f;
        __syncthreads();
        float vs = 0.f, vd = 0.f;
        if (n < N_NODES) {
            float acc = 0.f;
#pragma unroll
            for (int k = 0; k < HID; ++k) acc += hs[j][k] * wreg[k];
            g_h2[(size_t)n * HID + c] = acc;
            vs = acc * asc; vd = acc * adc;
        }
#pragma unroll
        for (int off = 16; off > 0; off >>= 1) {
            vs += __shfl_down_sync(0xffffffffu, vs, off);
            vd += __shfl_down_sync(0xffffffffu, vd, off);
        }
        if ((tid & 31) == 0) { sred_s[tid >> 5] = vs; sred_d[tid >> 5] = vd; }
        __syncthreads();
        if (n < N_NODES && c == 0) {
            g_al2s[n] = sred_s[2 * j] + sred_s[2 * j + 1];
            g_al2d[n] = sred_d[2 * j] + sred_d[2 * j + 1];
        }
        __syncthreads();
    }
}

// ---------------- K6: edge pass, layer 2 ----------------
__global__ void k_edge2(const int* __restrict__ src, const int* __restrict__ dst) {
    int t = blockIdx.x * blockDim.x + threadIdx.x;
    int e = t >> 4;
    if (e >= N_EI) return;
    int l = t & 15;
    int s, d;
    if (e < N_EDGES) { s = src[e]; d = dst[e]; }
    else             { s = d = e - N_EDGES; }
    float al = g_al2s[s] + g_al2d[d];
    float ee = al > 0.f ? al : NEG_SLOPE * al;
    float w = __expf(ee);
    float4 hv = *reinterpret_cast<const float4*>(&g_h2[s * HID + l * 4]);
    red_add_v4(&g_acc2[d * HID + l * 4], hv.x * w, hv.y * w, hv.z * w, hv.w * w);
    if (l == 0) red_add_f(&g_den2[d], w);
}

// ---------------- K7: finish layer 2 + global mean pool (batch sorted) ----------------
__global__ void k_fin2_pool(const float* __restrict__ b2, const int* __restrict__ batch) {
    int c = threadIdx.x & 63;
    int j = threadIdx.x >> 6;       // 0..3
    int n0 = blockIdx.x * 64;
    float b2c = b2[c];
    float runs = 0.f, runc = 0.f;
    int curb = -1;
    for (int it = 0; it < 16; ++it) {
        int n = n0 + j + it * 4;
        if (n >= N_NODES) break;
        int b = batch[n];
        float v = g_acc2[(size_t)n * HID + c] / (g_den2[n] + 1e-16f) + b2c;
        v = v > 0.f ? v : expm1f(v);
        if (b != curb) {
            if (curb >= 0) {
                red_add_f(&g_pool[curb * HID + c], runs);
                if (c == 0) red_add_f(&g_cnt[curb], runc);
            }
            curb = b; runs = 0.f; runc = 0.f;
        }
        runs += v; runc += 1.f;
    }
    if (curb >= 0) {
        red_add_f(&g_pool[curb * HID + c], runs);
        if (c == 0) red_add_f(&g_cnt[curb], runc);
    }
}

// ---------------- K8: classifier + log_softmax ----------------
__global__ void k_cls(const float* __restrict__ Wc, const float* __restrict__ bc,
                      float* __restrict__ out) {
    __shared__ float Ws[HID * NCLS];
    __shared__ float bs[NCLS];
    for (int i = threadIdx.x; i < HID * NCLS; i += blockDim.x) Ws[i] = Wc[i];
    if (threadIdx.x < NCLS) bs[threadIdx.x] = bc[threadIdx.x];
    __syncthreads();
    int g = threadIdx.x;
    if (g >= NG) return;
    float inv = 1.f / fmaxf(g_cnt[g], 1.f);
    float logit[NCLS];
#pragma unroll
    for (int q = 0; q < NCLS; ++q) logit[q] = bs[q];
    for (int c = 0; c < HID; ++c) {
        float pv = g_pool[g * HID + c] * inv;
#pragma unroll
        for (int q = 0; q < NCLS; ++q) logit[q] += pv * Ws[c * NCLS + q];
    }
    float m = logit[0];
#pragma unroll
    for (int q = 1; q < NCLS; ++q) m = fmaxf(m, logit[q]);
    float ssum = 0.f;
#pragma unroll
    for (int q = 0; q < NCLS; ++q) ssum += expf(logit[q] - m);
    float lse = m + logf(ssum);
#pragma unroll
    for (int q = 0; q < NCLS; ++q) out[g * NCLS + q] = logit[q] - lse;
}

// ---------------- launcher ----------------
extern "C" void kernel_launch(void* const* d_in, const int* in_sizes, int n_in,
                              void* d_out, int out_size) {
    const float* x      = (const float*)d_in[0];
    const int*   ei     = (const int*)  d_in[1];
    const int*   batch  = (const int*)  d_in[2];
    const float* W1     = (const float*)d_in[3];
    const float* a_src1 = (const float*)d_in[4];
    const float* a_dst1 = (const float*)d_in[5];
    const float* b1     = (const float*)d_in[6];
    const float* W2     = (const float*)d_in[7];
    const float* a_src2 = (const float*)d_in[8];
    const float* a_dst2 = (const float*)d_in[9];
    const float* b2     = (const float*)d_in[10];
    const float* Wc     = (const float*)d_in[11];
    const float* bc     = (const float*)d_in[12];
    float* out = (float*)d_out;
    const int* srcp = ei;
    const int* dstp = ei + N_EDGES;

    k_zero<<<(N_NODES * HID / 4 + 255) / 256, 256>>>();
    k_gemm1<<<(N_NODES + BM - 1) / BM, 256>>>(x, W1);
    k_prep1<<<(N_NODES * 4 + 255) / 256, 256>>>(a_src1, a_dst1);
    k_edge1<<<(N_EI * 16 + 255) / 256, 256>>>(srcp, dstp);
    k_fin1<<<(N_NODES * HID + 255) / 256, 256>>>(b1);
    k_layer2_mm<<<1480, 256>>>(W2, a_src2, a_dst2);
    k_edge2<<<(N_EI * 16 + 255) / 256, 256>>>(srcp, dstp);
    k_fin2_pool<<<(N_NODES + 63) / 64, 256>>>(b2, batch);
    k_cls<<<1, 128>>>(Wc, bc, out);
}

// round 6
// speedup vs baseline: 1.8991x; 1.8991x over previous
#include <cuda_runtime.h>
#include <cuda_bf16.h>
#include <cstdint>
#include <cstddef>

#define N_NODES 50000
#define N_EDGES 1600000
#define N_EI    (N_EDGES + N_NODES)
#define VOCAB   5000
#define HID     64
#define HEADS   4
#define NG      128
#define NCLS    20
#define NEG_SLOPE 0.2f

#define KPAD 5024        // 5000 padded to multiple of 32
#define NKT  157         // ceil(5000/32)

// ---------------- scratch (static device globals; no allocation) ----------------
__device__ float g_h1pre[N_NODES * HID];    // x @ W1
__device__ float g_al1s[N_NODES * HEADS];
__device__ float g_al1d[N_NODES * HEADS];
__device__ float g_acc1[N_NODES * HID];     // layer-1 weighted sum accumulator
__device__ float g_den1[N_NODES * HEADS];   // layer-1 softmax denominators
__device__ float g_h[N_NODES * HID];        // layer-1 output (post ELU)
__device__ float g_h2[N_NODES * HID];       // h @ W2
__device__ float g_al2s[N_NODES];
__device__ float g_al2d[N_NODES];
__device__ float g_acc2[N_NODES * HID];
__device__ float g_den2[N_NODES];
__device__ float g_pool[NG * HID];
__device__ float g_cnt[NG];
// W1 split into bf16 hi/lo, TRANSPOSED to [HID][KPAD] (k contiguous), K-tail zeroed
__device__ __align__(16) __nv_bfloat16 g_w1h[HID * KPAD];
__device__ __align__(16) __nv_bfloat16 g_w1l[HID * KPAD];

// ---------------- helpers ----------------
__device__ __forceinline__ void red_add_v4(float* p, float a, float b, float c, float d) {
    asm volatile("red.global.add.v4.f32 [%0], {%1, %2, %3, %4};"
                 :: "l"(p), "f"(a), "f"(b), "f"(c), "f"(d) : "memory");
}
__device__ __forceinline__ void red_add_f(float* p, float v) {
    asm volatile("red.global.add.f32 [%0], %1;" :: "l"(p), "f"(v) : "memory");
}

#define MMA_BF16(c, a, b0, b1)                                                  \
    asm volatile("mma.sync.aligned.m16n8k16.row.col.f32.bf16.bf16.f32 "         \
        "{%0,%1,%2,%3}, {%4,%5,%6,%7}, {%8,%9}, {%0,%1,%2,%3};"                 \
        : "+f"((c)[0]), "+f"((c)[1]), "+f"((c)[2]), "+f"((c)[3])                \
        : "r"((a)[0]), "r"((a)[1]), "r"((a)[2]), "r"((a)[3]), "r"(b0), "r"(b1))

__device__ __forceinline__ void ldsm_x4(uint32_t* r, uint32_t addr) {
    asm volatile("ldmatrix.sync.aligned.m8n8.x4.shared.b16 {%0,%1,%2,%3}, [%4];"
                 : "=r"(r[0]), "=r"(r[1]), "=r"(r[2]), "=r"(r[3]) : "r"(addr));
}

// ---------------- K0: zero all accumulators ----------------
__global__ void k_zero() {
    int i = blockIdx.x * blockDim.x + threadIdx.x;
    float4 z = make_float4(0.f, 0.f, 0.f, 0.f);
    if (i < N_NODES * HID / 4) {
        reinterpret_cast<float4*>(g_acc1)[i] = z;
        reinterpret_cast<float4*>(g_acc2)[i] = z;
    }
    if (i < N_NODES * HEADS / 4) reinterpret_cast<float4*>(g_den1)[i] = z;
    if (i < N_NODES / 4)         reinterpret_cast<float4*>(g_den2)[i] = z;
    if (i < NG * HID / 4)        reinterpret_cast<float4*>(g_pool)[i] = z;
    if (i < NG / 4)              reinterpret_cast<float4*>(g_cnt)[i]  = z;
}

// ---------------- K0b: split + transpose W1 -> g_w1h/g_w1l [HID][KPAD] ----------------
__global__ void k_prepW(const float* __restrict__ W1) {
    int i = blockIdx.x * blockDim.x + threadIdx.x;
    if (i >= HID * KPAD) return;
    int n = i / KPAD, k = i - n * KPAD;
    float v = (k < VOCAB) ? W1[(size_t)k * HID + n] : 0.f;
    __nv_bfloat16 h = __float2bfloat16(v);
    float r = v - __bfloat162float(h);
    g_w1h[i] = h;
    g_w1l[i] = __float2bfloat16(r);
}

// ---------------- K1: GEMM1 via bf16-split tensor-core MMA ----------------
// h1[50000,64] = x[50000,5000] @ W1[5000,64],  acc = xh*wh + xh*wl + xl*wh (fp32 acc)
// Tile: BM=128, BN=64, BK=32, 256 threads (8 warps, 16 rows/warp)
#define AROW 40   // smem row stride in bf16 elems (80B) -> conflict-free ldmatrix/LDS

__global__ __launch_bounds__(256) void k_gemm1_mma(const float* __restrict__ A) {
    __shared__ __align__(16) __nv_bfloat16 as_h[128 * AROW];
    __shared__ __align__(16) __nv_bfloat16 as_l[128 * AROW];
    __shared__ __align__(16) __nv_bfloat16 bs_h[64 * AROW];
    __shared__ __align__(16) __nv_bfloat16 bs_l[64 * AROW];

    const int tid  = threadIdx.x;
    const int lane = tid & 31;
    const int w    = tid >> 5;
    const int m0   = blockIdx.x * 128;

    float acc[8][4];
#pragma unroll
    for (int nt = 0; nt < 8; ++nt)
#pragma unroll
        for (int j = 0; j < 4; ++j) acc[nt][j] = 0.f;

    // staging registers for next tile
    float4 areg[4];
    uint4 bh_reg, bl_reg;

    const int a_row = tid >> 3;          // A tile row handled per iteration slot
    const int a_cq  = tid & 7;           // float4 column within row (0..7)
    const int b_n   = tid >> 2;          // B: n row
    const int b_kq  = tid & 3;           // B: 8-elem k group

    auto ldAB = [&](int kt) {
#pragma unroll
        for (int i = 0; i < 4; ++i) {
            int row = a_row + i * 32;
            int gr = m0 + row;
            int gk = kt + a_cq * 4;
            float4 v = make_float4(0.f, 0.f, 0.f, 0.f);
            if (gr < N_NODES && gk < VOCAB)
                v = *reinterpret_cast<const float4*>(&A[(size_t)gr * VOCAB + gk]);
            areg[i] = v;
        }
        bh_reg = *reinterpret_cast<const uint4*>(&g_w1h[b_n * KPAD + kt + b_kq * 8]);
        bl_reg = *reinterpret_cast<const uint4*>(&g_w1l[b_n * KPAD + kt + b_kq * 8]);
    };

    auto stAB = [&]() {
#pragma unroll
        for (int i = 0; i < 4; ++i) {
            int row = a_row + i * 32;
            float4 v = areg[i];
            __nv_bfloat16 h0 = __float2bfloat16(v.x);
            __nv_bfloat16 h1 = __float2bfloat16(v.y);
            __nv_bfloat16 h2 = __float2bfloat16(v.z);
            __nv_bfloat16 h3 = __float2bfloat16(v.w);
            __nv_bfloat16 l0 = __float2bfloat16(v.x - __bfloat162float(h0));
            __nv_bfloat16 l1 = __float2bfloat16(v.y - __bfloat162float(h1));
            __nv_bfloat16 l2 = __float2bfloat16(v.z - __bfloat162float(h2));
            __nv_bfloat16 l3 = __float2bfloat16(v.w - __bfloat162float(h3));
            __nv_bfloat162* ph = reinterpret_cast<__nv_bfloat162*>(&as_h[row * AROW + a_cq * 4]);
            ph[0] = __nv_bfloat162(h0, h1);
            ph[1] = __nv_bfloat162(h2, h3);
            __nv_bfloat162* pl = reinterpret_cast<__nv_bfloat162*>(&as_l[row * AROW + a_cq * 4]);
            pl[0] = __nv_bfloat162(l0, l1);
            pl[1] = __nv_bfloat162(l2, l3);
        }
        *reinterpret_cast<uint4*>(&bs_h[b_n * AROW + b_kq * 8]) = bh_reg;
        *reinterpret_cast<uint4*>(&bs_l[b_n * AROW + b_kq * 8]) = bl_reg;
    };

    const uint32_t as_h_u = (uint32_t)__cvta_generic_to_shared(as_h);
    const uint32_t as_l_u = (uint32_t)__cvta_generic_to_shared(as_l);
    // ldmatrix lane address pattern for 16x16 A fragment
    const uint32_t a_frag_off = (uint32_t)((w * 16 + (lane & 15)) * AROW * 2 + (lane >> 4) * 16);
    const int bn = lane >> 2;
    const int bk = (lane & 3) * 2;

    ldAB(0);
    stAB();
    __syncthreads();

    for (int it = 0; it < NKT; ++it) {
        if (it + 1 < NKT) ldAB((it + 1) * 32);

#pragma unroll
        for (int ks = 0; ks < 32; ks += 16) {
            uint32_t ah[4], al[4];
            ldsm_x4(ah, as_h_u + a_frag_off + ks * 2);
            ldsm_x4(al, as_l_u + a_frag_off + ks * 2);
#pragma unroll
            for (int nt = 0; nt < 8; ++nt) {
                const __nv_bfloat16* bp_h = &bs_h[(nt * 8 + bn) * AROW + ks + bk];
                const __nv_bfloat16* bp_l = &bs_l[(nt * 8 + bn) * AROW + ks + bk];
                uint32_t bh0 = *reinterpret_cast<const uint32_t*>(bp_h);
                uint32_t bh1 = *reinterpret_cast<const uint32_t*>(bp_h + 8);
                uint32_t bl0 = *reinterpret_cast<const uint32_t*>(bp_l);
                uint32_t bl1 = *reinterpret_cast<const uint32_t*>(bp_l + 8);
                MMA_BF16(acc[nt], ah, bh0, bh1);
                MMA_BF16(acc[nt], ah, bl0, bl1);
                MMA_BF16(acc[nt], al, bh0, bh1);
            }
        }
        __syncthreads();
        if (it + 1 < NKT) {
            stAB();
            __syncthreads();
        }
    }

    // store C: c0,c1 -> row r0 cols c..c+1; c2,c3 -> row r0+8
    const int r0 = m0 + w * 16 + (lane >> 2);
    const int c0 = 2 * (lane & 3);
#pragma unroll
    for (int nt = 0; nt < 8; ++nt) {
        int col = nt * 8 + c0;
        if (r0 < N_NODES)
            *reinterpret_cast<float2*>(&g_h1pre[(size_t)r0 * HID + col]) =
                make_float2(acc[nt][0], acc[nt][1]);
        if (r0 + 8 < N_NODES)
            *reinterpret_cast<float2*>(&g_h1pre[(size_t)(r0 + 8) * HID + col]) =
                make_float2(acc[nt][2], acc[nt][3]);
    }
}

// ---------------- K2: per-node attention logits, layer 1 ----------------
__global__ void k_prep1(const float* __restrict__ a_src1, const float* __restrict__ a_dst1) {
    __shared__ float as[HID], ad[HID];
    if (threadIdx.x < HID) { as[threadIdx.x] = a_src1[threadIdx.x]; ad[threadIdx.x] = a_dst1[threadIdx.x]; }
    __syncthreads();
    int t = blockIdx.x * blockDim.x + threadIdx.x;
    int n = t >> 2, p = t & 3;       // p = head
    if (n >= N_NODES) return;
    const float4* hp = reinterpret_cast<const float4*>(&g_h1pre[n * HID + p * 16]);
    float s = 0.f, d = 0.f;
#pragma unroll
    for (int q = 0; q < 4; ++q) {
        float4 v = hp[q];
        int b = p * 16 + q * 4;
        s += v.x * as[b] + v.y * as[b + 1] + v.z * as[b + 2] + v.w * as[b + 3];
        d += v.x * ad[b] + v.y * ad[b + 1] + v.z * ad[b + 2] + v.w * ad[b + 3];
    }
    g_al1s[n * HEADS + p] = s;
    g_al1d[n * HEADS + p] = d;
}

// ---------------- K3: edge pass, layer 1 (16 threads / edge) ----------------
__global__ void k_edge1(const int* __restrict__ src, const int* __restrict__ dst) {
    int t = blockIdx.x * blockDim.x + threadIdx.x;
    int e = t >> 4;
    if (e >= N_EI) return;
    int l = t & 15;
    int s, d;
    if (e < N_EDGES) { s = src[e]; d = dst[e]; }
    else             { s = d = e - N_EDGES; }        // self loops
    int head = l >> 2;
    float al = g_al1s[s * HEADS + head] + g_al1d[d * HEADS + head];
    float ee = al > 0.f ? al : NEG_SLOPE * al;
    float w = __expf(ee);
    float4 hv = *reinterpret_cast<const float4*>(&g_h1pre[s * HID + l * 4]);
    red_add_v4(&g_acc1[d * HID + l * 4], hv.x * w, hv.y * w, hv.z * w, hv.w * w);
    if ((l & 3) == 0) red_add_f(&g_den1[d * HEADS + head], w);
}

// ---------------- K4: finish layer 1 (normalize + bias + ELU) ----------------
__global__ void k_fin1(const float* __restrict__ b1) {
    int i = blockIdx.x * blockDim.x + threadIdx.x;
    if (i >= N_NODES * HID) return;
    int n = i >> 6, c = i & 63;
    float v = g_acc1[i] / (g_den1[(n << 2) + (c >> 4)] + 1e-16f) + b1[c];
    g_h[i] = v > 0.f ? v : expm1f(v);
}

// ---------------- K5: GEMM2 (h @ W2) + layer-2 attention logits ----------------
__global__ __launch_bounds__(256) void k_layer2_mm(const float* __restrict__ W2,
                                                   const float* __restrict__ as2,
                                                   const float* __restrict__ ad2) {
    __shared__ float hs[4][HID];
    __shared__ float sred_s[8], sred_d[8];
    int tid = threadIdx.x;
    int c = tid & 63;
    int j = tid >> 6;  // node lane 0..3
    float wreg[HID];
#pragma unroll
    for (int k = 0; k < HID; ++k) wreg[k] = W2[k * HID + c];
    float asc = as2[c], adc = ad2[c];

    for (int n0 = blockIdx.x * 4; n0 < N_NODES; n0 += gridDim.x * 4) {
        int n = n0 + j;
        hs[j][c] = (n < N_NODES) ? g_h[(size_t)n * HID + c] : 0.f;
        __syncthreads();
        float vs = 0.f, vd = 0.f;
        if (n < N_NODES) {
            float acc = 0.f;
#pragma unroll
            for (int k = 0; k < HID; ++k) acc += hs[j][k] * wreg[k];
            g_h2[(size_t)n * HID + c] = acc;
            vs = acc * asc; vd = acc * adc;
        }
#pragma unroll
        for (int off = 16; off > 0; off >>= 1) {
            vs += __shfl_down_sync(0xffffffffu, vs, off);
            vd += __shfl_down_sync(0xffffffffu, vd, off);
        }
        if ((tid & 31) == 0) { sred_s[tid >> 5] = vs; sred_d[tid >> 5] = vd; }
        __syncthreads();
        if (n < N_NODES && c == 0) {
            g_al2s[n] = sred_s[2 * j] + sred_s[2 * j + 1];
            g_al2d[n] = sred_d[2 * j] + sred_d[2 * j + 1];
        }
        __syncthreads();
    }
}

// ---------------- K6: edge pass, layer 2 ----------------
__global__ void k_edge2(const int* __restrict__ src, const int* __restrict__ dst) {
    int t = blockIdx.x * blockDim.x + threadIdx.x;
    int e = t >> 4;
    if (e >= N_EI) return;
    int l = t & 15;
    int s, d;
    if (e < N_EDGES) { s = src[e]; d = dst[e]; }
    else             { s = d = e - N_EDGES; }
    float al = g_al2s[s] + g_al2d[d];
    float ee = al > 0.f ? al : NEG_SLOPE * al;
    float w = __expf(ee);
    float4 hv = *reinterpret_cast<const float4*>(&g_h2[s * HID + l * 4]);
    red_add_v4(&g_acc2[d * HID + l * 4], hv.x * w, hv.y * w, hv.z * w, hv.w * w);
    if (l == 0) red_add_f(&g_den2[d], w);
}

// ---------------- K7: finish layer 2 + global mean pool (batch sorted) ----------------
__global__ void k_fin2_pool(const float* __restrict__ b2, const int* __restrict__ batch) {
    int c = threadIdx.x & 63;
    int j = threadIdx.x >> 6;       // 0..3
    int n0 = blockIdx.x * 64;
    float b2c = b2[c];
    float runs = 0.f, runc = 0.f;
    int curb = -1;
    for (int it = 0; it < 16; ++it) {
        int n = n0 + j + it * 4;
        if (n >= N_NODES) break;
        int b = batch[n];
        float v = g_acc2[(size_t)n * HID + c] / (g_den2[n] + 1e-16f) + b2c;
        v = v > 0.f ? v : expm1f(v);
        if (b != curb) {
            if (curb >= 0) {
                red_add_f(&g_pool[curb * HID + c], runs);
                if (c == 0) red_add_f(&g_cnt[curb], runc);
            }
            curb = b; runs = 0.f; runc = 0.f;
        }
        runs += v; runc += 1.f;
    }
    if (curb >= 0) {
        red_add_f(&g_pool[curb * HID + c], runs);
        if (c == 0) red_add_f(&g_cnt[curb], runc);
    }
}

// ---------------- K8: classifier + log_softmax ----------------
__global__ void k_cls(const float* __restrict__ Wc, const float* __restrict__ bc,
                      float* __restrict__ out) {
    __shared__ float Ws[HID * NCLS];
    __shared__ float bs[NCLS];
    for (int i = threadIdx.x; i < HID * NCLS; i += blockDim.x) Ws[i] = Wc[i];
    if (threadIdx.x < NCLS) bs[threadIdx.x] = bc[threadIdx.x];
    __syncthreads();
    int g = threadIdx.x;
    if (g >= NG) return;
    float inv = 1.f / fmaxf(g_cnt[g], 1.f);
    float logit[NCLS];
#pragma unroll
    for (int q = 0; q < NCLS; ++q) logit[q] = bs[q];
    for (int c = 0; c < HID; ++c) {
        float pv = g_pool[g * HID + c] * inv;
#pragma unroll
        for (int q = 0; q < NCLS; ++q) logit[q] += pv * Ws[c * NCLS + q];
    }
    float m = logit[0];
#pragma unroll
    for (int q = 1; q < NCLS; ++q) m = fmaxf(m, logit[q]);
    float ssum = 0.f;
#pragma unroll
    for (int q = 0; q < NCLS; ++q) ssum += expf(logit[q] - m);
    float lse = m + logf(ssum);
#pragma unroll
    for (int q = 0; q < NCLS; ++q) out[g * NCLS + q] = logit[q] - lse;
}

// ---------------- launcher ----------------
extern "C" void kernel_launch(void* const* d_in, const int* in_sizes, int n_in,
                              void* d_out, int out_size) {
    const float* x      = (const float*)d_in[0];
    const int*   ei     = (const int*)  d_in[1];
    const int*   batch  = (const int*)  d_in[2];
    const float* W1     = (const float*)d_in[3];
    const float* a_src1 = (const float*)d_in[4];
    const float* a_dst1 = (const float*)d_in[5];
    const float* b1     = (const float*)d_in[6];
    const float* W2     = (const float*)d_in[7];
    const float* a_src2 = (const float*)d_in[8];
    const float* a_dst2 = (const float*)d_in[9];
    const float* b2     = (const float*)d_in[10];
    const float* Wc     = (const float*)d_in[11];
    const float* bc     = (const float*)d_in[12];
    float* out = (float*)d_out;
    const int* srcp = ei;
    const int* dstp = ei + N_EDGES;

    k_zero<<<(N_NODES * HID / 4 + 255) / 256, 256>>>();
    k_prepW<<<(HID * KPAD + 255) / 256, 256>>>(W1);
    k_gemm1_mma<<<(N_NODES + 127) / 128, 256>>>(x);
    k_prep1<<<(N_NODES * 4 + 255) / 256, 256>>>(a_src1, a_dst1);
    k_edge1<<<(N_EI * 16 + 255) / 256, 256>>>(srcp, dstp);
    k_fin1<<<(N_NODES * HID + 255) / 256, 256>>>(b1);
    k_layer2_mm<<<1480, 256>>>(W2, a_src2, a_dst2);
    k_edge2<<<(N_EI * 16 + 255) / 256, 256>>>(srcp, dstp);
    k_fin2_pool<<<(N_NODES + 63) / 64, 256>>>(b2, batch);
    k_cls<<<1, 128>>>(Wc, bc, out);
}

// round 12
// speedup vs baseline: 2.0513x; 1.0801x over previous
#include <cuda_runtime.h>
#include <cuda_fp16.h>
#include <cstdint>
#include <cstddef>

#define N_NODES 50000
#define N_EDGES 1600000
#define N_EI    (N_EDGES + N_NODES)
#define VOCAB   5000
#define HID     64
#define HEADS   4
#define NG      128
#define NCLS    20
#define NEG_SLOPE 0.2f

#define KPAD 5024        // 5000 padded to multiple of 32
#define NKT  157         // ceil(5000/32)

// ---------------- scratch (static device globals; no allocation) ----------------
__device__ float g_h1pre[N_NODES * HID];    // x @ W1
__device__ float g_al1s[N_NODES * HEADS];
__device__ float g_al1d[N_NODES * HEADS];
__device__ float g_acc1[N_NODES * HID];     // layer-1 weighted sum accumulator
__device__ float g_den1[N_NODES * HEADS];   // layer-1 softmax denominators
__device__ float g_h[N_NODES * HID];        // layer-1 output (post ELU)
__device__ float g_h2[N_NODES * HID];       // h @ W2
__device__ float g_al2s[N_NODES];
__device__ float g_al2d[N_NODES];
__device__ float g_acc2[N_NODES * HID];
__device__ float g_den2[N_NODES];
__device__ float g_pool[NG * HID];
__device__ float g_cnt[NG];
// W1 in fp16, TRANSPOSED to [HID][KPAD] (k contiguous), K-tail zeroed
__device__ __align__(16) __half g_w1[HID * KPAD];

// ---------------- helpers ----------------
__device__ __forceinline__ void red_add_v4(float* p, float a, float b, float c, float d) {
    asm volatile("red.global.add.v4.f32 [%0], {%1, %2, %3, %4};"
                 :: "l"(p), "f"(a), "f"(b), "f"(c), "f"(d) : "memory");
}
__device__ __forceinline__ void red_add_f(float* p, float v) {
    asm volatile("red.global.add.f32 [%0], %1;" :: "l"(p), "f"(v) : "memory");
}

#define MMA_F16(c, a, b0, b1)                                                   \
    asm volatile("mma.sync.aligned.m16n8k16.row.col.f32.f16.f16.f32 "           \
        "{%0,%1,%2,%3}, {%4,%5,%6,%7}, {%8,%9}, {%0,%1,%2,%3};"                 \
        : "+f"((c)[0]), "+f"((c)[1]), "+f"((c)[2]), "+f"((c)[3])                \
        : "r"((a)[0]), "r"((a)[1]), "r"((a)[2]), "r"((a)[3]), "r"(b0), "r"(b1))

__device__ __forceinline__ void ldsm_x4(uint32_t* r, uint32_t addr) {
    asm volatile("ldmatrix.sync.aligned.m8n8.x4.shared.b16 {%0,%1,%2,%3}, [%4];"
                 : "=r"(r[0]), "=r"(r[1]), "=r"(r[2]), "=r"(r[3]) : "r"(addr));
}
__device__ __forceinline__ uint32_t pack_h2(__half a, __half b) {
    __half2 t(a, b);
    return *reinterpret_cast<uint32_t*>(&t);
}

// ---------------- K0: zero all accumulators ----------------
__global__ void k_zero() {
    int i = blockIdx.x * blockDim.x + threadIdx.x;
    float4 z = make_float4(0.f, 0.f, 0.f, 0.f);
    if (i < N_NODES * HID / 4) {
        reinterpret_cast<float4*>(g_acc1)[i] = z;
        reinterpret_cast<float4*>(g_acc2)[i] = z;
    }
    if (i < N_NODES * HEADS / 4) reinterpret_cast<float4*>(g_den1)[i] = z;
    if (i < N_NODES / 4)         reinterpret_cast<float4*>(g_den2)[i] = z;
    if (i < NG * HID / 4)        reinterpret_cast<float4*>(g_pool)[i] = z;
    if (i < NG / 4)              reinterpret_cast<float4*>(g_cnt)[i]  = z;
}

// ---------------- K0b: convert + transpose W1 -> g_w1 [HID][KPAD] fp16 ----------------
__global__ void k_prepW(const float* __restrict__ W1) {
    int i = blockIdx.x * blockDim.x + threadIdx.x;
    if (i >= HID * KPAD) return;
    int n = i / KPAD, k = i - n * KPAD;
    float v = (k < VOCAB) ? W1[(size_t)k * HID + n] : 0.f;
    g_w1[i] = __float2half_rn(v);
}

// ---------------- K1: GEMM1 via fp16 tensor-core MMA, A split hi/lo ----------------
// h1[50000,64] = x[50000,5000] @ W1[5000,64],  acc = (xh + xl) * w  (fp32 acc)
// Tile: BM=128, BN=64, BK=32, 256 threads (8 warps, 16 rows/warp)
// Epilogue fuses the layer-1 attention logit dot products (k_prep1).
#define AROW 40   // smem row stride in halfs (80B) -> conflict-free ldmatrix/LDS

__global__ __launch_bounds__(256) void k_gemm1_mma(const float* __restrict__ A,
                                                   const float* __restrict__ a_src1,
                                                   const float* __restrict__ a_dst1) {
    __shared__ __align__(16) __half as_h[128 * AROW];
    __shared__ __align__(16) __half as_l[128 * AROW];
    __shared__ __align__(16) __half bs[64 * AROW];
    __shared__ float s_as[HID], s_ad[HID];

    const int tid  = threadIdx.x;
    const int lane = tid & 31;
    const int w    = tid >> 5;
    const int m0   = blockIdx.x * 128;

    if (tid < HID) { s_as[tid] = a_src1[tid]; s_ad[tid] = a_dst1[tid]; }

    float acc[8][4];
#pragma unroll
    for (int nt = 0; nt < 8; ++nt)
#pragma unroll
        for (int j = 0; j < 4; ++j) acc[nt][j] = 0.f;

    // staging registers for next tile
    float4 areg[4];
    uint4 b_reg;

    const int a_row = tid >> 3;          // A tile row handled per iteration slot
    const int a_cq  = tid & 7;           // float4 column within row (0..7)
    const int b_n   = tid >> 2;          // B: n row
    const int b_kq  = tid & 3;           // B: 8-elem k group

    auto ldAB = [&](int kt) {
#pragma unroll
        for (int i = 0; i < 4; ++i) {
            int row = a_row + i * 32;
            int gr = m0 + row;
            int gk = kt + a_cq * 4;
            float4 v = make_float4(0.f, 0.f, 0.f, 0.f);
            if (gr < N_NODES && gk < VOCAB)
                v = *reinterpret_cast<const float4*>(&A[(size_t)gr * VOCAB + gk]);
            areg[i] = v;
        }
        b_reg = *reinterpret_cast<const uint4*>(&g_w1[b_n * KPAD + kt + b_kq * 8]);
    };

    auto stAB = [&]() {
#pragma unroll
        for (int i = 0; i < 4; ++i) {
            int row = a_row + i * 32;
            float4 v = areg[i];
            __half h0 = __float2half_rn(v.x);
            __half h1 = __float2half_rn(v.y);
            __half h2 = __float2half_rn(v.z);
            __half h3 = __float2half_rn(v.w);
            __half l0 = __float2half_rn(v.x - __half2float(h0));
            __half l1 = __float2half_rn(v.y - __half2float(h1));
            __half l2 = __float2half_rn(v.z - __half2float(h2));
            __half l3 = __float2half_rn(v.w - __half2float(h3));
            *reinterpret_cast<uint2*>(&as_h[row * AROW + a_cq * 4]) =
                make_uint2(pack_h2(h0, h1), pack_h2(h2, h3));
            *reinterpret_cast<uint2*>(&as_l[row * AROW + a_cq * 4]) =
                make_uint2(pack_h2(l0, l1), pack_h2(l2, l3));
        }
        *reinterpret_cast<uint4*>(&bs[b_n * AROW + b_kq * 8]) = b_reg;
    };

    const uint32_t as_h_u = (uint32_t)__cvta_generic_to_shared(as_h);
    const uint32_t as_l_u = (uint32_t)__cvta_generic_to_shared(as_l);
    // ldmatrix lane address pattern for 16x16 A fragment
    const uint32_t a_frag_off = (uint32_t)((w * 16 + (lane & 15)) * AROW * 2 + (lane >> 4) * 16);
    const int bn = lane >> 2;
    const int bk = (lane & 3) * 2;

    ldAB(0);
    stAB();
    __syncthreads();

    for (int it = 0; it < NKT; ++it) {
        if (it + 1 < NKT) ldAB((it + 1) * 32);

#pragma unroll
        for (int ks = 0; ks < 32; ks += 16) {
            uint32_t ah[4], al[4];
            ldsm_x4(ah, as_h_u + a_frag_off + ks * 2);
            ldsm_x4(al, as_l_u + a_frag_off + ks * 2);
#pragma unroll
            for (int nt = 0; nt < 8; ++nt) {
                const __half* bp = &bs[(nt * 8 + bn) * AROW + ks + bk];
                uint32_t b0 = *reinterpret_cast<const uint32_t*>(bp);
                uint32_t b1 = *reinterpret_cast<const uint32_t*>(bp + 8);
                MMA_F16(acc[nt], ah, b0, b1);
                MMA_F16(acc[nt], al, b0, b1);
            }
        }
        __syncthreads();
        if (it + 1 < NKT) {
            stAB();
            __syncthreads();
        }
    }

    // ---- store C + fused attention logits ----
    // thread holds cols {nt*8+c0, nt*8+c0+1} for rows r0 (acc[nt][0..1]) and r0+8 (acc[nt][2..3])
    const int r0 = m0 + w * 16 + (lane >> 2);
    const int c0 = 2 * (lane & 3);
#pragma unroll
    for (int nt = 0; nt < 8; ++nt) {
        int col = nt * 8 + c0;
        if (r0 < N_NODES)
            *reinterpret_cast<float2*>(&g_h1pre[(size_t)r0 * HID + col]) =
                make_float2(acc[nt][0], acc[nt][1]);
        if (r0 + 8 < N_NODES)
            *reinterpret_cast<float2*>(&g_h1pre[(size_t)(r0 + 8) * HID + col]) =
                make_float2(acc[nt][2], acc[nt][3]);
    }

    // per-head partial dot products: head p covers cols p*16..p*16+15 (nt = 2p, 2p+1)
    float ps[HEADS][2], pd[HEADS][2];
#pragma unroll
    for (int p = 0; p < HEADS; ++p) {
#pragma unroll
        for (int rr = 0; rr < 2; ++rr) {
            float s = 0.f, d = 0.f;
#pragma unroll
            for (int ntl = 0; ntl < 2; ++ntl) {
                int nt = 2 * p + ntl;
#pragma unroll
                for (int cc = 0; cc < 2; ++cc) {
                    int col = nt * 8 + c0 + cc;
                    float v = acc[nt][rr * 2 + cc];
                    s += v * s_as[col];
                    d += v * s_ad[col];
                }
            }
            ps[p][rr] = s; pd[p][rr] = d;
        }
    }
    // reduce across the 4-lane quad (lanes share r0; c0 spans the 8-col groups)
#pragma unroll
    for (int off = 1; off <= 2; off <<= 1) {
#pragma unroll
        for (int p = 0; p < HEADS; ++p) {
#pragma unroll
            for (int rr = 0; rr < 2; ++rr) {
                ps[p][rr] += __shfl_xor_sync(0xffffffffu, ps[p][rr], off);
                pd[p][rr] += __shfl_xor_sync(0xffffffffu, pd[p][rr], off);
            }
        }
    }
    const int q = lane & 3;   // this lane writes head q
    if (r0 < N_NODES) {
        g_al1s[r0 * HEADS + q] = ps[q][0];
        g_al1d[r0 * HEADS + q] = pd[q][0];
    }
    if (r0 + 8 < N_NODES) {
        g_al1s[(r0 + 8) * HEADS + q] = ps[q][1];
        g_al1d[(r0 + 8) * HEADS + q] = pd[q][1];
    }
}

// ---------------- K3: edge pass, layer 1 (16 threads / edge) ----------------
__global__ void k_edge1(const int* __restrict__ src, const int* __restrict__ dst) {
    int t = blockIdx.x * blockDim.x + threadIdx.x;
    int e = t >> 4;
    if (e >= N_EI) return;
    int l = t & 15;
    int s, d;
    if (e < N_EDGES) { s = src[e]; d = dst[e]; }
    else             { s = d = e - N_EDGES; }        // self loops
    int head = l >> 2;
    float al = g_al1s[s * HEADS + head] + g_al1d[d * HEADS + head];
    float ee = al > 0.f ? al : NEG_SLOPE * al;
    float w = __expf(ee);
    float4 hv = *reinterpret_cast<const float4*>(&g_h1pre[s * HID + l * 4]);
    red_add_v4(&g_acc1[d * HID + l * 4], hv.x * w, hv.y * w, hv.z * w, hv.w * w);
    if ((l & 3) == 0) red_add_f(&g_den1[d * HEADS + head], w);
}

// ---------------- K4: finish layer 1 (normalize + bias + ELU) ----------------
__global__ void k_fin1(const float* __restrict__ b1) {
    int i = blockIdx.x * blockDim.x + threadIdx.x;
    if (i >= N_NODES * HID) return;
    int n = i >> 6, c = i & 63;
    float v = g_acc1[i] / (g_den1[(n << 2) + (c >> 4)] + 1e-16f) + b1[c];
    g_h[i] = v > 0.f ? v : expm1f(v);
}

// ---------------- K5: GEMM2 (h @ W2) + layer-2 attention logits ----------------
__global__ __launch_bounds__(256) void k_layer2_mm(const float* __restrict__ W2,
                                                   const float* __restrict__ as2,
                                                   const float* __restrict__ ad2) {
    __shared__ float hs[4][HID];
    __shared__ float sred_s[8], sred_d[8];
    int tid = threadIdx.x;
    int c = tid & 63;
    int j = tid >> 6;  // node lane 0..3
    float wreg[HID];
#pragma unroll
    for (int k = 0; k < HID; ++k) wreg[k] = W2[k * HID + c];
    float asc = as2[c], adc = ad2[c];

    for (int n0 = blockIdx.x * 4; n0 < N_NODES; n0 += gridDim.x * 4) {
        int n = n0 + j;
        hs[j][c] = (n < N_NODES) ? g_h[(size_t)n * HID + c] : 0.f;
        __syncthreads();
        float vs = 0.f, vd = 0.f;
        if (n < N_NODES) {
            float acc = 0.f;
#pragma unroll
            for (int k = 0; k < HID; ++k) acc += hs[j][k] * wreg[k];
            g_h2[(size_t)n * HID + c] = acc;
            vs = acc * asc; vd = acc * adc;
        }
#pragma unroll
        for (int off = 16; off > 0; off >>= 1) {
            vs += __shfl_down_sync(0xffffffffu, vs, off);
            vd += __shfl_down_sync(0xffffffffu, vd, off);
        }
        if ((tid & 31) == 0) { sred_s[tid >> 5] = vs; sred_d[tid >> 5] = vd; }
        __syncthreads();
        if (n < N_NODES && c == 0) {
            g_al2s[n] = sred_s[2 * j] + sred_s[2 * j + 1];
            g_al2d[n] = sred_d[2 * j] + sred_d[2 * j + 1];
        }
        __syncthreads();
    }
}

// ---------------- K6: edge pass, layer 2 ----------------
__global__ void k_edge2(const int* __restrict__ src, const int* __restrict__ dst) {
    int t = blockIdx.x * blockDim.x + threadIdx.x;
    int e = t >> 4;
    if (e >= N_EI) return;
    int l = t & 15;
    int s, d;
    if (e < N_EDGES) { s = src[e]; d = dst[e]; }
    else             { s = d = e - N_EDGES; }
    float al = g_al2s[s] + g_al2d[d];
    float ee = al > 0.f ? al : NEG_SLOPE * al;
    float w = __expf(ee);
    float4 hv = *reinterpret_cast<const float4*>(&g_h2[s * HID + l * 4]);
    red_add_v4(&g_acc2[d * HID + l * 4], hv.x * w, hv.y * w, hv.z * w, hv.w * w);
    if (l == 0) red_add_f(&g_den2[d], w);
}

// ---------------- K7: finish layer 2 + global mean pool (batch sorted) ----------------
__global__ void k_fin2_pool(const float* __restrict__ b2, const int* __restrict__ batch) {
    int c = threadIdx.x & 63;
    int j = threadIdx.x >> 6;       // 0..3
    int n0 = blockIdx.x * 64;
    float b2c = b2[c];
    float runs = 0.f, runc = 0.f;
    int curb = -1;
    for (int it = 0; it < 16; ++it) {
        int n = n0 + j + it * 4;
        if (n >= N_NODES) break;
        int b = batch[n];
        float v = g_acc2[(size_t)n * HID + c] / (g_den2[n] + 1e-16f) + b2c;
        v = v > 0.f ? v : expm1f(v);
        if (b != curb) {
            if (curb >= 0) {
                red_add_f(&g_pool[curb * HID + c], runs);
                if (c == 0) red_add_f(&g_cnt[curb], runc);
            }
            curb = b; runs = 0.f; runc = 0.f;
        }
        runs += v; runc += 1.f;
    }
    if (curb >= 0) {
        red_add_f(&g_pool[curb * HID + c], runs);
        if (c == 0) red_add_f(&g_cnt[curb], runc);
    }
}

// ---------------- K8: classifier + log_softmax ----------------
__global__ void k_cls(const float* __restrict__ Wc, const float* __restrict__ bc,
                      float* __restrict__ out) {
    __shared__ float Ws[HID * NCLS];
    __shared__ float bs[NCLS];
    for (int i = threadIdx.x; i < HID * NCLS; i += blockDim.x) Ws[i] = Wc[i];
    if (threadIdx.x < NCLS) bs[threadIdx.x] = bc[threadIdx.x];
    __syncthreads();
    int g = threadIdx.x;
    if (g >= NG) return;
    float inv = 1.f / fmaxf(g_cnt[g], 1.f);
    float logit[NCLS];
#pragma unroll
    for (int q = 0; q < NCLS; ++q) logit[q] = bs[q];
    for (int c = 0; c < HID; ++c) {
        float pv = g_pool[g * HID + c] * inv;
#pragma unroll
        for (int q = 0; q < NCLS; ++q) logit[q] += pv * Ws[c * NCLS + q];
    }
    float m = logit[0];
#pragma unroll
    for (int q = 1; q < NCLS; ++q) m = fmaxf(m, logit[q]);
    float ssum = 0.f;
#pragma unroll
    for (int q = 0; q < NCLS; ++q) ssum += expf(logit[q] - m);
    float lse = m + logf(ssum);
#pragma unroll
    for (int q = 0; q < NCLS; ++q) out[g * NCLS + q] = logit[q] - lse;
}

// ---------------- launcher ----------------
extern "C" void kernel_launch(void* const* d_in, const int* in_sizes, int n_in,
                              void* d_out, int out_size) {
    const float* x      = (const float*)d_in[0];
    const int*   ei     = (const int*)  d_in[1];
    const int*   batch  = (const int*)  d_in[2];
    const float* W1     = (const float*)d_in[3];
    const float* a_src1 = (const float*)d_in[4];
    const float* a_dst1 = (const float*)d_in[5];
    const float* b1     = (const float*)d_in[6];
    const float* W2     = (const float*)d_in[7];
    const float* a_src2 = (const float*)d_in[8];
    const float* a_dst2 = (const float*)d_in[9];
    const float* b2     = (const float*)d_in[10];
    const float* Wc     = (const float*)d_in[11];
    const float* bc     = (const float*)d_in[12];
    float* out = (float*)d_out;
    const int* srcp = ei;
    const int* dstp = ei + N_EDGES;

    k_zero<<<(N_NODES * HID / 4 + 255) / 256, 256>>>();
    k_prepW<<<(HID * KPAD + 255) / 256, 256>>>(W1);
    k_gemm1_mma<<<(N_NODES + 127) / 128, 256>>>(x, a_src1, a_dst1);
    k_edge1<<<(N_EI * 16 + 255) / 256, 256>>>(srcp, dstp);
    k_fin1<<<(N_NODES * HID + 255) / 256, 256>>>(b1);
    k_layer2_mm<<<1480, 256>>>(W2, a_src2, a_dst2);
    k_edge2<<<(N_EI * 16 + 255) / 256, 256>>>(srcp, dstp);
    k_fin2_pool<<<(N_NODES + 63) / 64, 256>>>(b2, batch);
    k_cls<<<1, 128>>>(Wc, bc, out);
}

// round 13
// speedup vs baseline: 2.1515x; 1.0488x over previous
#include <cuda_runtime.h>
#include <cuda_fp16.h>
#include <cstdint>
#include <cstddef>

#define N_NODES 50000
#define N_EDGES 1600000
#define VOCAB   5000
#define HID     64
#define HEADS   4
#define NG      128
#define NCLS    20
#define NEG_SLOPE 0.2f

#define KPAD 5024        // 5000 padded to multiple of 32
#define NKT  157         // ceil(5000/32)

// ---------------- scratch (static device globals; no allocation) ----------------
__device__ float g_h1pre[N_NODES * HID];    // x @ W1
__device__ float g_al1s[N_NODES * HEADS];
__device__ float g_al1d[N_NODES * HEADS];
__device__ float g_h[N_NODES * HID];        // layer-1 output (post ELU)
__device__ float g_h2[N_NODES * HID];       // h @ W2
__device__ float g_al2s[N_NODES];
__device__ float g_al2d[N_NODES];
__device__ float g_pool[NG * HID];
__device__ float g_cnt[NG];
// CSR (dst-sorted edges)
__device__ int g_rowptr[N_NODES + 1];
__device__ int g_cursor[N_NODES];
__device__ int g_ssrc[N_EDGES];
// W1 in fp16, TRANSPOSED to [HID][KPAD] (k contiguous), K-tail zeroed
__device__ __align__(16) __half g_w1[HID * KPAD];

// ---------------- helpers ----------------
__device__ __forceinline__ void red_add_v2(float* p, float a, float b) {
    asm volatile("red.global.add.v2.f32 [%0], {%1, %2};" :: "l"(p), "f"(a), "f"(b) : "memory");
}
__device__ __forceinline__ void red_add_f(float* p, float v) {
    asm volatile("red.global.add.f32 [%0], %1;" :: "l"(p), "f"(v) : "memory");
}

#define MMA_F16(c, a, b0, b1)                                                   \
    asm volatile("mma.sync.aligned.m16n8k16.row.col.f32.f16.f16.f32 "           \
        "{%0,%1,%2,%3}, {%4,%5,%6,%7}, {%8,%9}, {%0,%1,%2,%3};"                 \
        : "+f"((c)[0]), "+f"((c)[1]), "+f"((c)[2]), "+f"((c)[3])                \
        : "r"((a)[0]), "r"((a)[1]), "r"((a)[2]), "r"((a)[3]), "r"(b0), "r"(b1))

__device__ __forceinline__ void ldsm_x4(uint32_t* r, uint32_t addr) {
    asm volatile("ldmatrix.sync.aligned.m8n8.x4.shared.b16 {%0,%1,%2,%3}, [%4];"
                 : "=r"(r[0]), "=r"(r[1]), "=r"(r[2]), "=r"(r[3]) : "r"(addr));
}
__device__ __forceinline__ uint32_t pack_h2(__half a, __half b) {
    __half2 t(a, b);
    return *reinterpret_cast<uint32_t*>(&t);
}

// ---------------- Kz: zero bins + pool + cnt ----------------
__global__ void k_zs() {
    int i = blockIdx.x * blockDim.x + threadIdx.x;
    if (i < N_NODES)   g_cursor[i] = 0;
    if (i < NG * HID)  g_pool[i] = 0.f;
    if (i < NG)        g_cnt[i] = 0.f;
}

// ---------------- Kh: histogram of dst ----------------
__global__ void k_hist(const int* __restrict__ dst) {
    int e = blockIdx.x * blockDim.x + threadIdx.x;
    if (e < N_EDGES) atomicAdd(&g_cursor[dst[e]], 1);
}

// ---------------- Ks: exclusive scan over bins (single block, 1024 threads) ----------------
__global__ __launch_bounds__(1024) void k_scan() {
    __shared__ int wsum[32];
    __shared__ int s_run;
    int tid = threadIdx.x, lane = tid & 31, wid = tid >> 5;
    if (tid == 0) s_run = 0;
    __syncthreads();
    for (int base = 0; base < N_NODES; base += 1024) {
        int i = base + tid;
        int v = (i < N_NODES) ? g_cursor[i] : 0;
        int x = v;
#pragma unroll
        for (int o = 1; o < 32; o <<= 1) {
            int y = __shfl_up_sync(0xffffffffu, x, o);
            if (lane >= o) x += y;
        }
        if (lane == 31) wsum[wid] = x;
        __syncthreads();
        if (wid == 0) {
            int s = wsum[lane];
#pragma unroll
            for (int o = 1; o < 32; o <<= 1) {
                int y = __shfl_up_sync(0xffffffffu, s, o);
                if (lane >= o) s += y;
            }
            wsum[lane] = s;
        }
        __syncthreads();
        int excl = x - v + (wid > 0 ? wsum[wid - 1] : 0) + s_run;
        if (i < N_NODES) { g_rowptr[i] = excl; g_cursor[i] = excl; }
        __syncthreads();
        if (tid == 0) s_run += wsum[31];
        __syncthreads();
    }
    if (tid == 0) g_rowptr[N_NODES] = s_run;
}

// ---------------- Kc: scatter edges into dst-sorted order ----------------
__global__ void k_scatter(const int* __restrict__ src, const int* __restrict__ dst) {
    int e = blockIdx.x * blockDim.x + threadIdx.x;
    if (e < N_EDGES) {
        int p = atomicAdd(&g_cursor[dst[e]], 1);
        g_ssrc[p] = src[e];
    }
}

// ---------------- K0b: convert + transpose W1 -> g_w1 [HID][KPAD] fp16 ----------------
__global__ void k_prepW(const float* __restrict__ W1) {
    int i = blockIdx.x * blockDim.x + threadIdx.x;
    if (i >= HID * KPAD) return;
    int n = i / KPAD, k = i - n * KPAD;
    float v = (k < VOCAB) ? W1[(size_t)k * HID + n] : 0.f;
    g_w1[i] = __float2half_rn(v);
}

// ---------------- K1: GEMM1 via fp16 tensor-core MMA, A split hi/lo ----------------
// h1[50000,64] = x @ W1, acc = (xh + xl)*w (fp32 acc). Epilogue fuses attention logits.
#define AROW 40

__global__ __launch_bounds__(256) void k_gemm1_mma(const float* __restrict__ A,
                                                   const float* __restrict__ a_src1,
                                                   const float* __restrict__ a_dst1) {
    __shared__ __align__(16) __half as_h[128 * AROW];
    __shared__ __align__(16) __half as_l[128 * AROW];
    __shared__ __align__(16) __half bs[64 * AROW];
    __shared__ float s_as[HID], s_ad[HID];

    const int tid  = threadIdx.x;
    const int lane = tid & 31;
    const int w    = tid >> 5;
    const int m0   = blockIdx.x * 128;

    if (tid < HID) { s_as[tid] = a_src1[tid]; s_ad[tid] = a_dst1[tid]; }

    float acc[8][4];
#pragma unroll
    for (int nt = 0; nt < 8; ++nt)
#pragma unroll
        for (int j = 0; j < 4; ++j) acc[nt][j] = 0.f;

    float4 areg[4];
    uint4 b_reg;

    const int a_row = tid >> 3;
    const int a_cq  = tid & 7;
    const int b_n   = tid >> 2;
    const int b_kq  = tid & 3;

    auto ldAB = [&](int kt) {
#pragma unroll
        for (int i = 0; i < 4; ++i) {
            int row = a_row + i * 32;
            int gr = m0 + row;
            int gk = kt + a_cq * 4;
            float4 v = make_float4(0.f, 0.f, 0.f, 0.f);
            if (gr < N_NODES && gk < VOCAB)
                v = *reinterpret_cast<const float4*>(&A[(size_t)gr * VOCAB + gk]);
            areg[i] = v;
        }
        b_reg = *reinterpret_cast<const uint4*>(&g_w1[b_n * KPAD + kt + b_kq * 8]);
    };

    auto stAB = [&]() {
#pragma unroll
        for (int i = 0; i < 4; ++i) {
            int row = a_row + i * 32;
            float4 v = areg[i];
            __half h0 = __float2half_rn(v.x);
            __half h1 = __float2half_rn(v.y);
            __half h2 = __float2half_rn(v.z);
            __half h3 = __float2half_rn(v.w);
            __half l0 = __float2half_rn(v.x - __half2float(h0));
            __half l1 = __float2half_rn(v.y - __half2float(h1));
            __half l2 = __float2half_rn(v.z - __half2float(h2));
            __half l3 = __float2half_rn(v.w - __half2float(h3));
            *reinterpret_cast<uint2*>(&as_h[row * AROW + a_cq * 4]) =
                make_uint2(pack_h2(h0, h1), pack_h2(h2, h3));
            *reinterpret_cast<uint2*>(&as_l[row * AROW + a_cq * 4]) =
                make_uint2(pack_h2(l0, l1), pack_h2(l2, l3));
        }
        *reinterpret_cast<uint4*>(&bs[b_n * AROW + b_kq * 8]) = b_reg;
    };

    const uint32_t as_h_u = (uint32_t)__cvta_generic_to_shared(as_h);
    const uint32_t as_l_u = (uint32_t)__cvta_generic_to_shared(as_l);
    const uint32_t a_frag_off = (uint32_t)((w * 16 + (lane & 15)) * AROW * 2 + (lane >> 4) * 16);
    const int bn = lane >> 2;
    const int bk = (lane & 3) * 2;

    ldAB(0);
    stAB();
    __syncthreads();

    for (int it = 0; it < NKT; ++it) {
        if (it + 1 < NKT) ldAB((it + 1) * 32);

#pragma unroll
        for (int ks = 0; ks < 32; ks += 16) {
            uint32_t ah[4], al[4];
            ldsm_x4(ah, as_h_u + a_frag_off + ks * 2);
            ldsm_x4(al, as_l_u + a_frag_off + ks * 2);
#pragma unroll
            for (int nt = 0; nt < 8; ++nt) {
                const __half* bp = &bs[(nt * 8 + bn) * AROW + ks + bk];
                uint32_t b0 = *reinterpret_cast<const uint32_t*>(bp);
                uint32_t b1 = *reinterpret_cast<const uint32_t*>(bp + 8);
                MMA_F16(acc[nt], ah, b0, b1);
                MMA_F16(acc[nt], al, b0, b1);
            }
        }
        __syncthreads();
        if (it + 1 < NKT) {
            stAB();
            __syncthreads();
        }
    }

    const int r0 = m0 + w * 16 + (lane >> 2);
    const int c0 = 2 * (lane & 3);
#pragma unroll
    for (int nt = 0; nt < 8; ++nt) {
        int col = nt * 8 + c0;
        if (r0 < N_NODES)
            *reinterpret_cast<float2*>(&g_h1pre[(size_t)r0 * HID + col]) =
                make_float2(acc[nt][0], acc[nt][1]);
        if (r0 + 8 < N_NODES)
            *reinterpret_cast<float2*>(&g_h1pre[(size_t)(r0 + 8) * HID + col]) =
                make_float2(acc[nt][2], acc[nt][3]);
    }

    // fused attention logits
    float ps[HEADS][2], pd[HEADS][2];
#pragma unroll
    for (int p = 0; p < HEADS; ++p) {
#pragma unroll
        for (int rr = 0; rr < 2; ++rr) {
            float s = 0.f, d = 0.f;
#pragma unroll
            for (int ntl = 0; ntl < 2; ++ntl) {
                int nt = 2 * p + ntl;
#pragma unroll
                for (int cc = 0; cc < 2; ++cc) {
                    int col = nt * 8 + c0 + cc;
                    float v = acc[nt][rr * 2 + cc];
                    s += v * s_as[col];
                    d += v * s_ad[col];
                }
            }
            ps[p][rr] = s; pd[p][rr] = d;
        }
    }
#pragma unroll
    for (int off = 1; off <= 2; off <<= 1) {
#pragma unroll
        for (int p = 0; p < HEADS; ++p) {
#pragma unroll
            for (int rr = 0; rr < 2; ++rr) {
                ps[p][rr] += __shfl_xor_sync(0xffffffffu, ps[p][rr], off);
                pd[p][rr] += __shfl_xor_sync(0xffffffffu, pd[p][rr], off);
            }
        }
    }
    const int q = lane & 3;
    if (r0 < N_NODES) {
        g_al1s[r0 * HEADS + q] = ps[q][0];
        g_al1d[r0 * HEADS + q] = pd[q][0];
    }
    if (r0 + 8 < N_NODES) {
        g_al1s[(r0 + 8) * HEADS + q] = ps[q][1];
        g_al1d[(r0 + 8) * HEADS + q] = pd[q][1];
    }
}

// ---------------- K3: edge pass layer 1, CSR warp-per-node, fused fin1 ----------------
// warp handles dst node n; lane covers cols {2*lane, 2*lane+1}, head = lane>>3
__global__ __launch_bounds__(256) void k_edge1_csr(const float* __restrict__ b1) {
    __shared__ float s_b1[HID];
    if (threadIdx.x < HID) s_b1[threadIdx.x] = b1[threadIdx.x];
    __syncthreads();

    int n = blockIdx.x * 8 + (threadIdx.x >> 5);
    if (n >= N_NODES) return;
    int lane = threadIdx.x & 31;
    int c0 = 2 * lane;
    int head = lane >> 3;

    float aldn = g_al1d[n * HEADS + head];
    // self loop
    float al = g_al1s[n * HEADS + head] + aldn;
    float ee = al > 0.f ? al : NEG_SLOPE * al;
    float wgt = __expf(ee);
    float2 hv = *reinterpret_cast<const float2*>(&g_h1pre[(size_t)n * HID + c0]);
    float ax = wgt * hv.x, ay = wgt * hv.y, den = wgt;

    int beg = g_rowptr[n], end = g_rowptr[n + 1];
    for (int base = beg; base < end; base += 32) {
        int rem = end - base;
        int j = base + lane;
        int s = (lane < rem) ? g_ssrc[j] : 0;
        if (rem >= 32) {
#pragma unroll 8
            for (int t = 0; t < 32; ++t) {
                int sj = __shfl_sync(0xffffffffu, s, t);
                float a2 = g_al1s[sj * HEADS + head] + aldn;
                float e2 = a2 > 0.f ? a2 : NEG_SLOPE * a2;
                float w2 = __expf(e2);
                float2 h2 = *reinterpret_cast<const float2*>(&g_h1pre[(size_t)sj * HID + c0]);
                ax += w2 * h2.x; ay += w2 * h2.y; den += w2;
            }
        } else {
            for (int t = 0; t < rem; ++t) {
                int sj = __shfl_sync(0xffffffffu, s, t);
                float a2 = g_al1s[sj * HEADS + head] + aldn;
                float e2 = a2 > 0.f ? a2 : NEG_SLOPE * a2;
                float w2 = __expf(e2);
                float2 h2 = *reinterpret_cast<const float2*>(&g_h1pre[(size_t)sj * HID + c0]);
                ax += w2 * h2.x; ay += w2 * h2.y; den += w2;
            }
        }
    }
    float inv = 1.f / (den + 1e-16f);
    float vx = ax * inv + s_b1[c0];
    float vy = ay * inv + s_b1[c0 + 1];
    vx = vx > 0.f ? vx : expm1f(vx);
    vy = vy > 0.f ? vy : expm1f(vy);
    *reinterpret_cast<float2*>(&g_h[(size_t)n * HID + c0]) = make_float2(vx, vy);
}

// ---------------- K5: GEMM2 (h @ W2) + layer-2 attention logits ----------------
__global__ __launch_bounds__(256) void k_layer2_mm(const float* __restrict__ W2,
                                                   const float* __restrict__ as2,
                                                   const float* __restrict__ ad2) {
    __shared__ float hs[4][HID];
    __shared__ float sred_s[8], sred_d[8];
    int tid = threadIdx.x;
    int c = tid & 63;
    int j = tid >> 6;
    float wreg[HID];
#pragma unroll
    for (int k = 0; k < HID; ++k) wreg[k] = W2[k * HID + c];
    float asc = as2[c], adc = ad2[c];

    for (int n0 = blockIdx.x * 4; n0 < N_NODES; n0 += gridDim.x * 4) {
        int n = n0 + j;
        hs[j][c] = (n < N_NODES) ? g_h[(size_t)n * HID + c] : 0.f;
        __syncthreads();
        float vs = 0.f, vd = 0.f;
        if (n < N_NODES) {
            float acc = 0.f;
#pragma unroll
            for (int k = 0; k < HID; ++k) acc += hs[j][k] * wreg[k];
            g_h2[(size_t)n * HID + c] = acc;
            vs = acc * asc; vd = acc * adc;
        }
#pragma unroll
        for (int off = 16; off > 0; off >>= 1) {
            vs += __shfl_down_sync(0xffffffffu, vs, off);
            vd += __shfl_down_sync(0xffffffffu, vd, off);
        }
        if ((tid & 31) == 0) { sred_s[tid >> 5] = vs; sred_d[tid >> 5] = vd; }
        __syncthreads();
        if (n < N_NODES && c == 0) {
            g_al2s[n] = sred_s[2 * j] + sred_s[2 * j + 1];
            g_al2d[n] = sred_d[2 * j] + sred_d[2 * j + 1];
        }
        __syncthreads();
    }
}

// ---------------- K6: edge pass layer 2, CSR warp-per-node, fused fin2 + pool ----------------
__global__ __launch_bounds__(256) void k_edge2_csr(const float* __restrict__ b2,
                                                   const int* __restrict__ batch) {
    __shared__ float s_b2[HID];
    if (threadIdx.x < HID) s_b2[threadIdx.x] = b2[threadIdx.x];
    __syncthreads();

    int n = blockIdx.x * 8 + (threadIdx.x >> 5);
    if (n >= N_NODES) return;
    int lane = threadIdx.x & 31;
    int c0 = 2 * lane;

    float aldn = g_al2d[n];
    float al = g_al2s[n] + aldn;
    float ee = al > 0.f ? al : NEG_SLOPE * al;
    float wgt = __expf(ee);
    float2 hv = *reinterpret_cast<const float2*>(&g_h2[(size_t)n * HID + c0]);
    float ax = wgt * hv.x, ay = wgt * hv.y, den = wgt;

    int beg = g_rowptr[n], end = g_rowptr[n + 1];
    for (int base = beg; base < end; base += 32) {
        int rem = end - base;
        int j = base + lane;
        int s = (lane < rem) ? g_ssrc[j] : 0;
        if (rem >= 32) {
#pragma unroll 8
            for (int t = 0; t < 32; ++t) {
                int sj = __shfl_sync(0xffffffffu, s, t);
                float a2 = g_al2s[sj] + aldn;
                float e2 = a2 > 0.f ? a2 : NEG_SLOPE * a2;
                float w2 = __expf(e2);
                float2 h2 = *reinterpret_cast<const float2*>(&g_h2[(size_t)sj * HID + c0]);
                ax += w2 * h2.x; ay += w2 * h2.y; den += w2;
            }
        } else {
            for (int t = 0; t < rem; ++t) {
                int sj = __shfl_sync(0xffffffffu, s, t);
                float a2 = g_al2s[sj] + aldn;
                float e2 = a2 > 0.f ? a2 : NEG_SLOPE * a2;
                float w2 = __expf(e2);
                float2 h2 = *reinterpret_cast<const float2*>(&g_h2[(size_t)sj * HID + c0]);
                ax += w2 * h2.x; ay += w2 * h2.y; den += w2;
            }
        }
    }
    float inv = 1.f / (den + 1e-16f);
    float vx = ax * inv + s_b2[c0];
    float vy = ay * inv + s_b2[c0 + 1];
    vx = vx > 0.f ? vx : expm1f(vx);
    vy = vy > 0.f ? vy : expm1f(vy);
    int b = batch[n];
    red_add_v2(&g_pool[b * HID + c0], vx, vy);
    if (lane == 0) red_add_f(&g_cnt[b], 1.f);
}

// ---------------- K8: classifier + log_softmax ----------------
__global__ void k_cls(const float* __restrict__ Wc, const float* __restrict__ bc,
                      float* __restrict__ out) {
    __shared__ float Ws[HID * NCLS];
    __shared__ float bs[NCLS];
    for (int i = threadIdx.x; i < HID * NCLS; i += blockDim.x) Ws[i] = Wc[i];
    if (threadIdx.x < NCLS) bs[threadIdx.x] = bc[threadIdx.x];
    __syncthreads();
    int g = threadIdx.x;
    if (g >= NG) return;
    float inv = 1.f / fmaxf(g_cnt[g], 1.f);
    float logit[NCLS];
#pragma unroll
    for (int q = 0; q < NCLS; ++q) logit[q] = bs[q];
    for (int c = 0; c < HID; ++c) {
        float pv = g_pool[g * HID + c] * inv;
#pragma unroll
        for (int q = 0; q < NCLS; ++q) logit[q] += pv * Ws[c * NCLS + q];
    }
    float m = logit[0];
#pragma unroll
    for (int q = 1; q < NCLS; ++q) m = fmaxf(m, logit[q]);
    float ssum = 0.f;
#pragma unroll
    for (int q = 0; q < NCLS; ++q) ssum += expf(logit[q] - m);
    float lse = m + logf(ssum);
#pragma unroll
    for (int q = 0; q < NCLS; ++q) out[g * NCLS + q] = logit[q] - lse;
}

// ---------------- launcher ----------------
extern "C" void kernel_launch(void* const* d_in, const int* in_sizes, int n_in,
                              void* d_out, int out_size) {
    const float* x      = (const float*)d_in[0];
    const int*   ei     = (const int*)  d_in[1];
    const int*   batch  = (const int*)  d_in[2];
    const float* W1     = (const float*)d_in[3];
    const float* a_src1 = (const float*)d_in[4];
    const float* a_dst1 = (const float*)d_in[5];
    const float* b1     = (const float*)d_in[6];
    const float* W2     = (const float*)d_in[7];
    const float* a_src2 = (const float*)d_in[8];
    const float* a_dst2 = (const float*)d_in[9];
    const float* b2     = (const float*)d_in[10];
    const float* Wc     = (const float*)d_in[11];
    const float* bc     = (const float*)d_in[12];
    float* out = (float*)d_out;
    const int* srcp = ei;
    const int* dstp = ei + N_EDGES;

    k_zs<<<(N_NODES + 255) / 256, 256>>>();
    k_hist<<<(N_EDGES + 255) / 256, 256>>>(dstp);
    k_scan<<<1, 1024>>>();
    k_scatter<<<(N_EDGES + 255) / 256, 256>>>(srcp, dstp);
    k_prepW<<<(HID * KPAD + 255) / 256, 256>>>(W1);
    k_gemm1_mma<<<(N_NODES + 127) / 128, 256>>>(x, a_src1, a_dst1);
    k_edge1_csr<<<(N_NODES + 7) / 8, 256>>>(b1);
    k_layer2_mm<<<1480, 256>>>(W2, a_src2, a_dst2);
    k_edge2_csr<<<(N_NODES + 7) / 8, 256>>>(b2, batch);
    k_cls<<<1, 128>>>(Wc, bc, out);
}

// round 14
// speedup vs baseline: 2.7559x; 1.2809x over previous
#include <cuda_runtime.h>
#include <cuda_fp16.h>
#include <cstdint>
#include <cstddef>

#define N_NODES 50000
#define N_EDGES 1600000
#define VOCAB   5000
#define HID     64
#define HEADS   4
#define NG      128
#define NCLS    20
#define NEG_SLOPE 0.2f

#define KPAD 5024        // 5000 padded to multiple of 32
#define NKT  157         // ceil(5000/32)

// ---------------- scratch (static device globals; no allocation) ----------------
__device__ float g_h1pre[N_NODES * HID];    // x @ W1
__device__ float g_al1s[N_NODES * HEADS];
__device__ float g_al1d[N_NODES * HEADS];
__device__ float g_h[N_NODES * HID];        // layer-1 output (post ELU)
__device__ float g_h2[N_NODES * HID];       // h @ W2
__device__ float g_al2s[N_NODES];
__device__ float g_al2d[N_NODES];
__device__ float g_pool[NG * HID];
__device__ float g_cnt[NG];
// CSR (dst-sorted edges)
__device__ int g_rowptr[N_NODES + 1];
__device__ int g_cursor[N_NODES];
__device__ int g_ssrc[N_EDGES];
// W1 in fp16, TRANSPOSED to [HID][KPAD] (k contiguous), K-tail zeroed
__device__ __align__(16) __half g_w1[HID * KPAD];

// ---------------- helpers ----------------
__device__ __forceinline__ void red_add_v2(float* p, float a, float b) {
    asm volatile("red.global.add.v2.f32 [%0], {%1, %2};" :: "l"(p), "f"(a), "f"(b) : "memory");
}
__device__ __forceinline__ void red_add_f(float* p, float v) {
    asm volatile("red.global.add.f32 [%0], %1;" :: "l"(p), "f"(v) : "memory");
}

#define MMA_F16(c, a, b0, b1)                                                   \
    asm volatile("mma.sync.aligned.m16n8k16.row.col.f32.f16.f16.f32 "           \
        "{%0,%1,%2,%3}, {%4,%5,%6,%7}, {%8,%9}, {%0,%1,%2,%3};"                 \
        : "+f"((c)[0]), "+f"((c)[1]), "+f"((c)[2]), "+f"((c)[3])                \
        : "r"((a)[0]), "r"((a)[1]), "r"((a)[2]), "r"((a)[3]), "r"(b0), "r"(b1))

__device__ __forceinline__ void ldsm_x4(uint32_t* r, uint32_t addr) {
    asm volatile("ldmatrix.sync.aligned.m8n8.x4.shared.b16 {%0,%1,%2,%3}, [%4];"
                 : "=r"(r[0]), "=r"(r[1]), "=r"(r[2]), "=r"(r[3]) : "r"(addr));
}
__device__ __forceinline__ uint32_t pack_h2(__half a, __half b) {
    __half2 t(a, b);
    return *reinterpret_cast<uint32_t*>(&t);
}

// ---------------- Kz: zero bins + pool + cnt ----------------
__global__ void k_zs() {
    int i = blockIdx.x * blockDim.x + threadIdx.x;
    if (i < N_NODES)   g_cursor[i] = 0;
    if (i < NG * HID)  g_pool[i] = 0.f;
    if (i < NG)        g_cnt[i] = 0.f;
}

// ---------------- Kh: histogram of dst ----------------
__global__ void k_hist(const int* __restrict__ dst) {
    int e = blockIdx.x * blockDim.x + threadIdx.x;
    if (e < N_EDGES) atomicAdd(&g_cursor[dst[e]], 1);
}

// ---------------- Ks: exclusive scan over bins (single block, 1024 threads) ----------------
__global__ __launch_bounds__(1024) void k_scan() {
    __shared__ int wsum[32];
    __shared__ int s_run;
    int tid = threadIdx.x, lane = tid & 31, wid = tid >> 5;
    if (tid == 0) s_run = 0;
    __syncthreads();
    for (int base = 0; base < N_NODES; base += 1024) {
        int i = base + tid;
        int v = (i < N_NODES) ? g_cursor[i] : 0;
        int x = v;
#pragma unroll
        for (int o = 1; o < 32; o <<= 1) {
            int y = __shfl_up_sync(0xffffffffu, x, o);
            if (lane >= o) x += y;
        }
        if (lane == 31) wsum[wid] = x;
        __syncthreads();
        if (wid == 0) {
            int s = wsum[lane];
#pragma unroll
            for (int o = 1; o < 32; o <<= 1) {
                int y = __shfl_up_sync(0xffffffffu, s, o);
                if (lane >= o) s += y;
            }
            wsum[lane] = s;
        }
        __syncthreads();
        int excl = x - v + (wid > 0 ? wsum[wid - 1] : 0) + s_run;
        if (i < N_NODES) { g_rowptr[i] = excl; g_cursor[i] = excl; }
        __syncthreads();
        if (tid == 0) s_run += wsum[31];
        __syncthreads();
    }
    if (tid == 0) g_rowptr[N_NODES] = s_run;
}

// ---------------- Kc: scatter edges into dst-sorted order ----------------
__global__ void k_scatter(const int* __restrict__ src, const int* __restrict__ dst) {
    int e = blockIdx.x * blockDim.x + threadIdx.x;
    if (e < N_EDGES) {
        int p = atomicAdd(&g_cursor[dst[e]], 1);
        g_ssrc[p] = src[e];
    }
}

// ---------------- K0b: convert + transpose W1 -> g_w1 [HID][KPAD] fp16 ----------------
__global__ void k_prepW(const float* __restrict__ W1) {
    int i = blockIdx.x * blockDim.x + threadIdx.x;
    if (i >= HID * KPAD) return;
    int n = i / KPAD, k = i - n * KPAD;
    float v = (k < VOCAB) ? W1[(size_t)k * HID + n] : 0.f;
    g_w1[i] = __float2half_rn(v);
}

// ---------------- K1: GEMM1 via fp16 tensor-core MMA (pure fp16, fp32 acc) ----------------
// h1[50000,64] = x @ W1. Double-buffered smem, one __syncthreads per K-iter.
// Epilogue fuses the layer-1 attention logit dot products.
#define AROW 40

__global__ __launch_bounds__(256) void k_gemm1_mma(const float* __restrict__ A,
                                                   const float* __restrict__ a_src1,
                                                   const float* __restrict__ a_dst1) {
    __shared__ __align__(16) __half as[2][128 * AROW];
    __shared__ __align__(16) __half bs[2][64 * AROW];
    __shared__ float s_as[HID], s_ad[HID];

    const int tid  = threadIdx.x;
    const int lane = tid & 31;
    const int w    = tid >> 5;
    const int m0   = blockIdx.x * 128;

    if (tid < HID) { s_as[tid] = a_src1[tid]; s_ad[tid] = a_dst1[tid]; }

    float acc[8][4];
#pragma unroll
    for (int nt = 0; nt < 8; ++nt)
#pragma unroll
        for (int j = 0; j < 4; ++j) acc[nt][j] = 0.f;

    float4 areg[4];
    uint4 b_reg;

    const int a_row = tid >> 3;
    const int a_cq  = tid & 7;
    const int b_n   = tid >> 2;
    const int b_kq  = tid & 3;

    auto ldAB = [&](int kt) {
#pragma unroll
        for (int i = 0; i < 4; ++i) {
            int row = a_row + i * 32;
            int gr = m0 + row;
            int gk = kt + a_cq * 4;
            float4 v = make_float4(0.f, 0.f, 0.f, 0.f);
            if (gr < N_NODES && gk < VOCAB)
                v = *reinterpret_cast<const float4*>(&A[(size_t)gr * VOCAB + gk]);
            areg[i] = v;
        }
        b_reg = *reinterpret_cast<const uint4*>(&g_w1[b_n * KPAD + kt + b_kq * 8]);
    };

    auto stAB = [&](int buf) {
#pragma unroll
        for (int i = 0; i < 4; ++i) {
            int row = a_row + i * 32;
            float4 v = areg[i];
            *reinterpret_cast<uint2*>(&as[buf][row * AROW + a_cq * 4]) =
                make_uint2(pack_h2(__float2half_rn(v.x), __float2half_rn(v.y)),
                           pack_h2(__float2half_rn(v.z), __float2half_rn(v.w)));
        }
        *reinterpret_cast<uint4*>(&bs[buf][b_n * AROW + b_kq * 8]) = b_reg;
    };

    const uint32_t as_u0 = (uint32_t)__cvta_generic_to_shared(&as[0][0]);
    const uint32_t as_u1 = (uint32_t)__cvta_generic_to_shared(&as[1][0]);
    const uint32_t a_frag_off = (uint32_t)((w * 16 + (lane & 15)) * AROW * 2 + (lane >> 4) * 16);
    const int bn = lane >> 2;
    const int bk = (lane & 3) * 2;

    ldAB(0);
    stAB(0);
    __syncthreads();

    for (int it = 0; it < NKT; ++it) {
        const int buf = it & 1;
        if (it + 1 < NKT) ldAB((it + 1) * 32);

        const uint32_t as_u = buf ? as_u1 : as_u0;
        const __half* bsb = &bs[buf][0];
#pragma unroll
        for (int ks = 0; ks < 32; ks += 16) {
            uint32_t ah[4];
            ldsm_x4(ah, as_u + a_frag_off + ks * 2);
#pragma unroll
            for (int nt = 0; nt < 8; ++nt) {
                const __half* bp = &bsb[(nt * 8 + bn) * AROW + ks + bk];
                uint32_t b0 = *reinterpret_cast<const uint32_t*>(bp);
                uint32_t b1 = *reinterpret_cast<const uint32_t*>(bp + 8);
                MMA_F16(acc[nt], ah, b0, b1);
            }
        }
        if (it + 1 < NKT) stAB(buf ^ 1);
        __syncthreads();
    }

    const int r0 = m0 + w * 16 + (lane >> 2);
    const int c0 = 2 * (lane & 3);
#pragma unroll
    for (int nt = 0; nt < 8; ++nt) {
        int col = nt * 8 + c0;
        if (r0 < N_NODES)
            *reinterpret_cast<float2*>(&g_h1pre[(size_t)r0 * HID + col]) =
                make_float2(acc[nt][0], acc[nt][1]);
        if (r0 + 8 < N_NODES)
            *reinterpret_cast<float2*>(&g_h1pre[(size_t)(r0 + 8) * HID + col]) =
                make_float2(acc[nt][2], acc[nt][3]);
    }

    // fused attention logits
    float ps[HEADS][2], pd[HEADS][2];
#pragma unroll
    for (int p = 0; p < HEADS; ++p) {
#pragma unroll
        for (int rr = 0; rr < 2; ++rr) {
            float s = 0.f, d = 0.f;
#pragma unroll
            for (int ntl = 0; ntl < 2; ++ntl) {
                int nt = 2 * p + ntl;
#pragma unroll
                for (int cc = 0; cc < 2; ++cc) {
                    int col = nt * 8 + c0 + cc;
                    float v = acc[nt][rr * 2 + cc];
                    s += v * s_as[col];
                    d += v * s_ad[col];
                }
            }
            ps[p][rr] = s; pd[p][rr] = d;
        }
    }
#pragma unroll
    for (int off = 1; off <= 2; off <<= 1) {
#pragma unroll
        for (int p = 0; p < HEADS; ++p) {
#pragma unroll
            for (int rr = 0; rr < 2; ++rr) {
                ps[p][rr] += __shfl_xor_sync(0xffffffffu, ps[p][rr], off);
                pd[p][rr] += __shfl_xor_sync(0xffffffffu, pd[p][rr], off);
            }
        }
    }
    const int q = lane & 3;
    if (r0 < N_NODES) {
        g_al1s[r0 * HEADS + q] = ps[q][0];
        g_al1d[r0 * HEADS + q] = pd[q][0];
    }
    if (r0 + 8 < N_NODES) {
        g_al1s[(r0 + 8) * HEADS + q] = ps[q][1];
        g_al1d[(r0 + 8) * HEADS + q] = pd[q][1];
    }
}

// ---------------- K3: edge pass layer 1, CSR warp-per-node, fused fin1 ----------------
__global__ __launch_bounds__(256) void k_edge1_csr(const float* __restrict__ b1) {
    __shared__ float s_b1[HID];
    if (threadIdx.x < HID) s_b1[threadIdx.x] = b1[threadIdx.x];
    __syncthreads();

    int n = blockIdx.x * 8 + (threadIdx.x >> 5);
    if (n >= N_NODES) return;
    int lane = threadIdx.x & 31;
    int c0 = 2 * lane;
    int head = lane >> 3;

    float aldn = g_al1d[n * HEADS + head];
    float al = g_al1s[n * HEADS + head] + aldn;
    float ee = al > 0.f ? al : NEG_SLOPE * al;
    float wgt = __expf(ee);
    float2 hv = *reinterpret_cast<const float2*>(&g_h1pre[(size_t)n * HID + c0]);
    float ax = wgt * hv.x, ay = wgt * hv.y, den = wgt;

    int beg = g_rowptr[n], end = g_rowptr[n + 1];
    for (int base = beg; base < end; base += 32) {
        int rem = end - base;
        int j = base + lane;
        int s = (lane < rem) ? g_ssrc[j] : 0;
        if (rem >= 32) {
#pragma unroll 8
            for (int t = 0; t < 32; ++t) {
                int sj = __shfl_sync(0xffffffffu, s, t);
                float a2 = g_al1s[sj * HEADS + head] + aldn;
                float e2 = a2 > 0.f ? a2 : NEG_SLOPE * a2;
                float w2 = __expf(e2);
                float2 h2 = *reinterpret_cast<const float2*>(&g_h1pre[(size_t)sj * HID + c0]);
                ax += w2 * h2.x; ay += w2 * h2.y; den += w2;
            }
        } else {
            for (int t = 0; t < rem; ++t) {
                int sj = __shfl_sync(0xffffffffu, s, t);
                float a2 = g_al1s[sj * HEADS + head] + aldn;
                float e2 = a2 > 0.f ? a2 : NEG_SLOPE * a2;
                float w2 = __expf(e2);
                float2 h2 = *reinterpret_cast<const float2*>(&g_h1pre[(size_t)sj * HID + c0]);
                ax += w2 * h2.x; ay += w2 * h2.y; den += w2;
            }
        }
    }
    float inv = 1.f / (den + 1e-16f);
    float vx = ax * inv + s_b1[c0];
    float vy = ay * inv + s_b1[c0 + 1];
    vx = vx > 0.f ? vx : expm1f(vx);
    vy = vy > 0.f ? vy : expm1f(vy);
    *reinterpret_cast<float2*>(&g_h[(size_t)n * HID + c0]) = make_float2(vx, vy);
}

// ---------------- K5: GEMM2 (h @ W2) + layer-2 attention logits ----------------
__global__ __launch_bounds__(256) void k_layer2_mm(const float* __restrict__ W2,
                                                   const float* __restrict__ as2,
                                                   const float* __restrict__ ad2) {
    __shared__ float hs[4][HID];
    __shared__ float sred_s[8], sred_d[8];
    int tid = threadIdx.x;
    int c = tid & 63;
    int j = tid >> 6;
    float wreg[HID];
#pragma unroll
    for (int k = 0; k < HID; ++k) wreg[k] = W2[k * HID + c];
    float asc = as2[c], adc = ad2[c];

    for (int n0 = blockIdx.x * 4; n0 < N_NODES; n0 += gridDim.x * 4) {
        int n = n0 + j;
        hs[j][c] = (n < N_NODES) ? g_h[(size_t)n * HID + c] : 0.f;
        __syncthreads();
        float vs = 0.f, vd = 0.f;
        if (n < N_NODES) {
            float acc = 0.f;
#pragma unroll
            for (int k = 0; k < HID; ++k) acc += hs[j][k] * wreg[k];
            g_h2[(size_t)n * HID + c] = acc;
            vs = acc * asc; vd = acc * adc;
        }
#pragma unroll
        for (int off = 16; off > 0; off >>= 1) {
            vs += __shfl_down_sync(0xffffffffu, vs, off);
            vd += __shfl_down_sync(0xffffffffu, vd, off);
        }
        if ((tid & 31) == 0) { sred_s[tid >> 5] = vs; sred_d[tid >> 5] = vd; }
        __syncthreads();
        if (n < N_NODES && c == 0) {
            g_al2s[n] = sred_s[2 * j] + sred_s[2 * j + 1];
            g_al2d[n] = sred_d[2 * j] + sred_d[2 * j + 1];
        }
        __syncthreads();
    }
}

// ---------------- K6: edge pass layer 2, CSR warp-per-node, fused fin2 + pool ----------------
__global__ __launch_bounds__(256) void k_edge2_csr(const float* __restrict__ b2,
                                                   const int* __restrict__ batch) {
    __shared__ float s_b2[HID];
    if (threadIdx.x < HID) s_b2[threadIdx.x] = b2[threadIdx.x];
    __syncthreads();

    int n = blockIdx.x * 8 + (threadIdx.x >> 5);
    if (n >= N_NODES) return;
    int lane = threadIdx.x & 31;
    int c0 = 2 * lane;

    float aldn = g_al2d[n];
    float al = g_al2s[n] + aldn;
    float ee = al > 0.f ? al : NEG_SLOPE * al;
    float wgt = __expf(ee);
    float2 hv = *reinterpret_cast<const float2*>(&g_h2[(size_t)n * HID + c0]);
    float ax = wgt * hv.x, ay = wgt * hv.y, den = wgt;

    int beg = g_rowptr[n], end = g_rowptr[n + 1];
    for (int base = beg; base < end; base += 32) {
        int rem = end - base;
        int j = base + lane;
        int s = (lane < rem) ? g_ssrc[j] : 0;
        if (rem >= 32) {
#pragma unroll 8
            for (int t = 0; t < 32; ++t) {
                int sj = __shfl_sync(0xffffffffu, s, t);
                float a2 = g_al2s[sj] + aldn;
                float e2 = a2 > 0.f ? a2 : NEG_SLOPE * a2;
                float w2 = __expf(e2);
                float2 h2 = *reinterpret_cast<const float2*>(&g_h2[(size_t)sj * HID + c0]);
                ax += w2 * h2.x; ay += w2 * h2.y; den += w2;
            }
        } else {
            for (int t = 0; t < rem; ++t) {
                int sj = __shfl_sync(0xffffffffu, s, t);
                float a2 = g_al2s[sj] + aldn;
                float e2 = a2 > 0.f ? a2 : NEG_SLOPE * a2;
                float w2 = __expf(e2);
                float2 h2 = *reinterpret_cast<const float2*>(&g_h2[(size_t)sj * HID + c0]);
                ax += w2 * h2.x; ay += w2 * h2.y; den += w2;
            }
        }
    }
    float inv = 1.f / (den + 1e-16f);
    float vx = ax * inv + s_b2[c0];
    float vy = ay * inv + s_b2[c0 + 1];
    vx = vx > 0.f ? vx : expm1f(vx);
    vy = vy > 0.f ? vy : expm1f(vy);
    int b = batch[n];
    red_add_v2(&g_pool[b * HID + c0], vx, vy);
    if (lane == 0) red_add_f(&g_cnt[b], 1.f);
}

// ---------------- K8: classifier + log_softmax ----------------
__global__ void k_cls(const float* __restrict__ Wc, const float* __restrict__ bc,
                      float* __restrict__ out) {
    __shared__ float Ws[HID * NCLS];
    __shared__ float bs[NCLS];
    for (int i = threadIdx.x; i < HID * NCLS; i += blockDim.x) Ws[i] = Wc[i];
    if (threadIdx.x < NCLS) bs[threadIdx.x] = bc[threadIdx.x];
    __syncthreads();
    int g = threadIdx.x;
    if (g >= NG) return;
    float inv = 1.f / fmaxf(g_cnt[g], 1.f);
    float logit[NCLS];
#pragma unroll
    for (int q = 0; q < NCLS; ++q) logit[q] = bs[q];
    for (int c = 0; c < HID; ++c) {
        float pv = g_pool[g * HID + c] * inv;
#pragma unroll
        for (int q = 0; q < NCLS; ++q) logit[q] += pv * Ws[c * NCLS + q];
    }
    float m = logit[0];
#pragma unroll
    for (int q = 1; q < NCLS; ++q) m = fmaxf(m, logit[q]);
    float ssum = 0.f;
#pragma unroll
    for (int q = 0; q < NCLS; ++q) ssum += expf(logit[q] - m);
    float lse = m + logf(ssum);
#pragma unroll
    for (int q = 0; q < NCLS; ++q) out[g * NCLS + q] = logit[q] - lse;
}

// ---------------- launcher ----------------
extern "C" void kernel_launch(void* const* d_in, const int* in_sizes, int n_in,
                              void* d_out, int out_size) {
    const float* x      = (const float*)d_in[0];
    const int*   ei     = (const int*)  d_in[1];
    const int*   batch  = (const int*)  d_in[2];
    const float* W1     = (const float*)d_in[3];
    const float* a_src1 = (const float*)d_in[4];
    const float* a_dst1 = (const float*)d_in[5];
    const float* b1     = (const float*)d_in[6];
    const float* W2     = (const float*)d_in[7];
    const float* a_src2 = (const float*)d_in[8];
    const float* a_dst2 = (const float*)d_in[9];
    const float* b2     = (const float*)d_in[10];
    const float* Wc     = (const float*)d_in[11];
    const float* bc     = (const float*)d_in[12];
    float* out = (float*)d_out;
    const int* srcp = ei;
    const int* dstp = ei + N_EDGES;

    k_zs<<<(N_NODES + 255) / 256, 256>>>();
    k_hist<<<(N_EDGES + 255) / 256, 256>>>(dstp);
    k_scan<<<1, 1024>>>();
    k_scatter<<<(N_EDGES + 255) / 256, 256>>>(srcp, dstp);
    k_prepW<<<(HID * KPAD + 255) / 256, 256>>>(W1);
    k_gemm1_mma<<<(N_NODES + 127) / 128, 256>>>(x, a_src1, a_dst1);
    k_edge1_csr<<<(N_NODES + 7) / 8, 256>>>(b1);
    k_layer2_mm<<<1480, 256>>>(W2, a_src2, a_dst2);
    k_edge2_csr<<<(N_NODES + 7) / 8, 256>>>(b2, batch);
    k_cls<<<1, 128>>>(Wc, bc, out);
}

// round 15
// speedup vs baseline: 3.0959x; 1.1234x over previous
#include <cuda_runtime.h>
#include <cuda_fp16.h>
#include <cstdint>
#include <cstddef>

#define N_NODES 50000
#define N_EDGES 1600000
#define VOCAB   5000
#define HID     64
#define HEADS   4
#define NG      128
#define NCLS    20
#define NEG_SLOPE 0.2f

#define KPAD 5024        // 5000 padded to multiple of 32
#define NKT  157         // ceil(5000/32)

// ---------------- scratch (static device globals; no allocation) ----------------
__device__ float g_h1pre[N_NODES * HID];    // x @ W1
__device__ float g_al1s[N_NODES * HEADS];
__device__ float g_al1d[N_NODES * HEADS];
__device__ float g_h[N_NODES * HID];        // layer-1 output (post ELU)
__device__ float g_h2[N_NODES * HID];       // h @ W2
__device__ float g_al2s[N_NODES];
__device__ float g_al2d[N_NODES];
__device__ float g_pool[NG * HID];
__device__ float g_cnt[NG];
// CSR (dst-sorted edges)
__device__ int g_rowptr[N_NODES + 1];
__device__ int g_cursor[N_NODES];
__device__ int g_ssrc[N_EDGES];
// W1 in fp16, TRANSPOSED to [HID][KPAD] (k contiguous), K-tail zeroed
__device__ __align__(16) __half g_w1[HID * KPAD];

// ---------------- helpers ----------------
__device__ __forceinline__ void red_add_v2(float* p, float a, float b) {
    asm volatile("red.global.add.v2.f32 [%0], {%1, %2};" :: "l"(p), "f"(a), "f"(b) : "memory");
}
__device__ __forceinline__ void red_add_f(float* p, float v) {
    asm volatile("red.global.add.f32 [%0], %1;" :: "l"(p), "f"(v) : "memory");
}

#define MMA_F16(c, a, b0, b1)                                                   \
    asm volatile("mma.sync.aligned.m16n8k16.row.col.f32.f16.f16.f32 "           \
        "{%0,%1,%2,%3}, {%4,%5,%6,%7}, {%8,%9}, {%0,%1,%2,%3};"                 \
        : "+f"((c)[0]), "+f"((c)[1]), "+f"((c)[2]), "+f"((c)[3])                \
        : "r"((a)[0]), "r"((a)[1]), "r"((a)[2]), "r"((a)[3]), "r"(b0), "r"(b1))

__device__ __forceinline__ void ldsm_x4(uint32_t* r, uint32_t addr) {
    asm volatile("ldmatrix.sync.aligned.m8n8.x4.shared.b16 {%0,%1,%2,%3}, [%4];"
                 : "=r"(r[0]), "=r"(r[1]), "=r"(r[2]), "=r"(r[3]) : "r"(addr));
}
__device__ __forceinline__ uint32_t pack_h2(__half a, __half b) {
    __half2 t(a, b);
    return *reinterpret_cast<uint32_t*>(&t);
}

// ---------------- Kz: zero bins + pool + cnt ----------------
__global__ void k_zs() {
    int i = blockIdx.x * blockDim.x + threadIdx.x;
    if (i < N_NODES)   g_cursor[i] = 0;
    if (i < NG * HID)  g_pool[i] = 0.f;
    if (i < NG)        g_cnt[i] = 0.f;
}

// ---------------- Kh: histogram of dst ----------------
__global__ void k_hist(const int* __restrict__ dst) {
    int e = blockIdx.x * blockDim.x + threadIdx.x;
    if (e < N_EDGES) atomicAdd(&g_cursor[dst[e]], 1);
}

// ---------------- Ks: exclusive scan over bins (single block, 1024 threads) ----------------
__global__ __launch_bounds__(1024) void k_scan() {
    __shared__ int wsum[32];
    __shared__ int s_run;
    int tid = threadIdx.x, lane = tid & 31, wid = tid >> 5;
    if (tid == 0) s_run = 0;
    __syncthreads();
    for (int base = 0; base < N_NODES; base += 1024) {
        int i = base + tid;
        int v = (i < N_NODES) ? g_cursor[i] : 0;
        int x = v;
#pragma unroll
        for (int o = 1; o < 32; o <<= 1) {
            int y = __shfl_up_sync(0xffffffffu, x, o);
            if (lane >= o) x += y;
        }
        if (lane == 31) wsum[wid] = x;
        __syncthreads();
        if (wid == 0) {
            int s = wsum[lane];
#pragma unroll
            for (int o = 1; o < 32; o <<= 1) {
                int y = __shfl_up_sync(0xffffffffu, s, o);
                if (lane >= o) s += y;
            }
            wsum[lane] = s;
        }
        __syncthreads();
        int excl = x - v + (wid > 0 ? wsum[wid - 1] : 0) + s_run;
        if (i < N_NODES) { g_rowptr[i] = excl; g_cursor[i] = excl; }
        __syncthreads();
        if (tid == 0) s_run += wsum[31];
        __syncthreads();
    }
    if (tid == 0) g_rowptr[N_NODES] = s_run;
}

// ---------------- Kc: scatter edges into dst-sorted order ----------------
__global__ void k_scatter(const int* __restrict__ src, const int* __restrict__ dst) {
    int e = blockIdx.x * blockDim.x + threadIdx.x;
    if (e < N_EDGES) {
        int p = atomicAdd(&g_cursor[dst[e]], 1);
        g_ssrc[p] = src[e];
    }
}

// ---------------- K0b: convert + transpose W1 -> g_w1 [HID][KPAD] fp16 ----------------
__global__ void k_prepW(const float* __restrict__ W1) {
    int i = blockIdx.x * blockDim.x + threadIdx.x;
    if (i >= HID * KPAD) return;
    int n = i / KPAD, k = i - n * KPAD;
    float v = (k < VOCAB) ? W1[(size_t)k * HID + n] : 0.f;
    g_w1[i] = __float2half_rn(v);
}

// ---------------- K1: GEMM1 via fp16 tensor-core MMA (pure fp16, fp32 acc) ----------------
// h1[50000,64] = x @ W1. Double-buffered smem, one __syncthreads per K-iter.
// Epilogue fuses the layer-1 attention logit dot products.
#define AROW 40

__global__ __launch_bounds__(256) void k_gemm1_mma(const float* __restrict__ A,
                                                   const float* __restrict__ a_src1,
                                                   const float* __restrict__ a_dst1) {
    __shared__ __align__(16) __half as[2][128 * AROW];
    __shared__ __align__(16) __half bs[2][64 * AROW];
    __shared__ float s_as[HID], s_ad[HID];

    const int tid  = threadIdx.x;
    const int lane = tid & 31;
    const int w    = tid >> 5;
    const int m0   = blockIdx.x * 128;

    if (tid < HID) { s_as[tid] = a_src1[tid]; s_ad[tid] = a_dst1[tid]; }

    float acc[8][4];
#pragma unroll
    for (int nt = 0; nt < 8; ++nt)
#pragma unroll
        for (int j = 0; j < 4; ++j) acc[nt][j] = 0.f;

    float4 areg[4];
    uint4 b_reg;

    const int a_row = tid >> 3;
    const int a_cq  = tid & 7;
    const int b_n   = tid >> 2;
    const int b_kq  = tid & 3;

    auto ldAB = [&](int kt) {
#pragma unroll
        for (int i = 0; i < 4; ++i) {
            int row = a_row + i * 32;
            int gr = m0 + row;
            int gk = kt + a_cq * 4;
            float4 v = make_float4(0.f, 0.f, 0.f, 0.f);
            if (gr < N_NODES && gk < VOCAB)
                v = *reinterpret_cast<const float4*>(&A[(size_t)gr * VOCAB + gk]);
            areg[i] = v;
        }
        b_reg = *reinterpret_cast<const uint4*>(&g_w1[b_n * KPAD + kt + b_kq * 8]);
    };

    auto stAB = [&](int buf) {
#pragma unroll
        for (int i = 0; i < 4; ++i) {
            int row = a_row + i * 32;
            float4 v = areg[i];
            *reinterpret_cast<uint2*>(&as[buf][row * AROW + a_cq * 4]) =
                make_uint2(pack_h2(__float2half_rn(v.x), __float2half_rn(v.y)),
                           pack_h2(__float2half_rn(v.z), __float2half_rn(v.w)));
        }
        *reinterpret_cast<uint4*>(&bs[buf][b_n * AROW + b_kq * 8]) = b_reg;
    };

    const uint32_t as_u0 = (uint32_t)__cvta_generic_to_shared(&as[0][0]);
    const uint32_t as_u1 = (uint32_t)__cvta_generic_to_shared(&as[1][0]);
    const uint32_t a_frag_off = (uint32_t)((w * 16 + (lane & 15)) * AROW * 2 + (lane >> 4) * 16);
    const int bn = lane >> 2;
    const int bk = (lane & 3) * 2;

    ldAB(0);
    stAB(0);
    __syncthreads();

    for (int it = 0; it < NKT; ++it) {
        const int buf = it & 1;
        if (it + 1 < NKT) ldAB((it + 1) * 32);

        const uint32_t as_u = buf ? as_u1 : as_u0;
        const __half* bsb = &bs[buf][0];
#pragma unroll
        for (int ks = 0; ks < 32; ks += 16) {
            uint32_t ah[4];
            ldsm_x4(ah, as_u + a_frag_off + ks * 2);
#pragma unroll
            for (int nt = 0; nt < 8; ++nt) {
                const __half* bp = &bsb[(nt * 8 + bn) * AROW + ks + bk];
                uint32_t b0 = *reinterpret_cast<const uint32_t*>(bp);
                uint32_t b1 = *reinterpret_cast<const uint32_t*>(bp + 8);
                MMA_F16(acc[nt], ah, b0, b1);
            }
        }
        if (it + 1 < NKT) stAB(buf ^ 1);
        __syncthreads();
    }

    const int r0 = m0 + w * 16 + (lane >> 2);
    const int c0 = 2 * (lane & 3);
#pragma unroll
    for (int nt = 0; nt < 8; ++nt) {
        int col = nt * 8 + c0;
        if (r0 < N_NODES)
            *reinterpret_cast<float2*>(&g_h1pre[(size_t)r0 * HID + col]) =
                make_float2(acc[nt][0], acc[nt][1]);
        if (r0 + 8 < N_NODES)
            *reinterpret_cast<float2*>(&g_h1pre[(size_t)(r0 + 8) * HID + col]) =
                make_float2(acc[nt][2], acc[nt][3]);
    }

    // fused attention logits
    float ps[HEADS][2], pd[HEADS][2];
#pragma unroll
    for (int p = 0; p < HEADS; ++p) {
#pragma unroll
        for (int rr = 0; rr < 2; ++rr) {
            float s = 0.f, d = 0.f;
#pragma unroll
            for (int ntl = 0; ntl < 2; ++ntl) {
                int nt = 2 * p + ntl;
#pragma unroll
                for (int cc = 0; cc < 2; ++cc) {
                    int col = nt * 8 + c0 + cc;
                    float v = acc[nt][rr * 2 + cc];
                    s += v * s_as[col];
                    d += v * s_ad[col];
                }
            }
            ps[p][rr] = s; pd[p][rr] = d;
        }
    }
#pragma unroll
    for (int off = 1; off <= 2; off <<= 1) {
#pragma unroll
        for (int p = 0; p < HEADS; ++p) {
#pragma unroll
            for (int rr = 0; rr < 2; ++rr) {
                ps[p][rr] += __shfl_xor_sync(0xffffffffu, ps[p][rr], off);
                pd[p][rr] += __shfl_xor_sync(0xffffffffu, pd[p][rr], off);
            }
        }
    }
    const int q = lane & 3;
    if (r0 < N_NODES) {
        g_al1s[r0 * HEADS + q] = ps[q][0];
        g_al1d[r0 * HEADS + q] = pd[q][0];
    }
    if (r0 + 8 < N_NODES) {
        g_al1s[(r0 + 8) * HEADS + q] = ps[q][1];
        g_al1d[(r0 + 8) * HEADS + q] = pd[q][1];
    }
}

// ---------------- K3: edge pass layer 1, CSR warp-per-node, fused fin1 ----------------
__global__ __launch_bounds__(256) void k_edge1_csr(const float* __restrict__ b1) {
    __shared__ float s_b1[HID];
    if (threadIdx.x < HID) s_b1[threadIdx.x] = b1[threadIdx.x];
    __syncthreads();

    int n = blockIdx.x * 8 + (threadIdx.x >> 5);
    if (n >= N_NODES) return;
    int lane = threadIdx.x & 31;
    int c0 = 2 * lane;
    int head = lane >> 3;

    float aldn = g_al1d[n * HEADS + head];
    float al = g_al1s[n * HEADS + head] + aldn;
    float ee = al > 0.f ? al : NEG_SLOPE * al;
    float wgt = __expf(ee);
    float2 hv = *reinterpret_cast<const float2*>(&g_h1pre[(size_t)n * HID + c0]);
    float ax = wgt * hv.x, ay = wgt * hv.y, den = wgt;

    int beg = g_rowptr[n], end = g_rowptr[n + 1];
    for (int base = beg; base < end; base += 32) {
        int rem = end - base;
        int j = base + lane;
        int s = (lane < rem) ? g_ssrc[j] : 0;
        if (rem >= 32) {
#pragma unroll 8
            for (int t = 0; t < 32; ++t) {
                int sj = __shfl_sync(0xffffffffu, s, t);
                float a2 = g_al1s[sj * HEADS + head] + aldn;
                float e2 = a2 > 0.f ? a2 : NEG_SLOPE * a2;
                float w2 = __expf(e2);
                float2 h2 = *reinterpret_cast<const float2*>(&g_h1pre[(size_t)sj * HID + c0]);
                ax += w2 * h2.x; ay += w2 * h2.y; den += w2;
            }
        } else {
            for (int t = 0; t < rem; ++t) {
                int sj = __shfl_sync(0xffffffffu, s, t);
                float a2 = g_al1s[sj * HEADS + head] + aldn;
                float e2 = a2 > 0.f ? a2 : NEG_SLOPE * a2;
                float w2 = __expf(e2);
                float2 h2 = *reinterpret_cast<const float2*>(&g_h1pre[(size_t)sj * HID + c0]);
                ax += w2 * h2.x; ay += w2 * h2.y; den += w2;
            }
        }
    }
    float inv = 1.f / (den + 1e-16f);
    float vx = ax * inv + s_b1[c0];
    float vy = ay * inv + s_b1[c0 + 1];
    vx = vx > 0.f ? vx : expm1f(vx);
    vy = vy > 0.f ? vy : expm1f(vy);
    *reinterpret_cast<float2*>(&g_h[(size_t)n * HID + c0]) = make_float2(vx, vy);
}

// ---------------- K5: GEMM2 (h @ W2) + layer-2 attention logits ----------------
__global__ __launch_bounds__(256) void k_layer2_mm(const float* __restrict__ W2,
                                                   const float* __restrict__ as2,
                                                   const float* __restrict__ ad2) {
    __shared__ float hs[4][HID];
    __shared__ float sred_s[8], sred_d[8];
    int tid = threadIdx.x;
    int c = tid & 63;
    int j = tid >> 6;
    float wreg[HID];
#pragma unroll
    for (int k = 0; k < HID; ++k) wreg[k] = W2[k * HID + c];
    float asc = as2[c], adc = ad2[c];

    for (int n0 = blockIdx.x * 4; n0 < N_NODES; n0 += gridDim.x * 4) {
        int n = n0 + j;
        hs[j][c] = (n < N_NODES) ? g_h[(size_t)n * HID + c] : 0.f;
        __syncthreads();
        float vs = 0.f, vd = 0.f;
        if (n < N_NODES) {
            float acc = 0.f;
#pragma unroll
            for (int k = 0; k < HID; ++k) acc += hs[j][k] * wreg[k];
            g_h2[(size_t)n * HID + c] = acc;
            vs = acc * asc; vd = acc * adc;
        }
#pragma unroll
        for (int off = 16; off > 0; off >>= 1) {
            vs += __shfl_down_sync(0xffffffffu, vs, off);
            vd += __shfl_down_sync(0xffffffffu, vd, off);
        }
        if ((tid & 31) == 0) { sred_s[tid >> 5] = vs; sred_d[tid >> 5] = vd; }
        __syncthreads();
        if (n < N_NODES && c == 0) {
            g_al2s[n] = sred_s[2 * j] + sred_s[2 * j + 1];
            g_al2d[n] = sred_d[2 * j] + sred_d[2 * j + 1];
        }
        __syncthreads();
    }
}

// ---------------- K6: edge pass layer 2, CSR warp-per-node, fused fin2 + pool ----------------
__global__ __launch_bounds__(256) void k_edge2_csr(const float* __restrict__ b2,
                                                   const int* __restrict__ batch) {
    __shared__ float s_b2[HID];
    if (threadIdx.x < HID) s_b2[threadIdx.x] = b2[threadIdx.x];
    __syncthreads();

    int n = blockIdx.x * 8 + (threadIdx.x >> 5);
    if (n >= N_NODES) return;
    int lane = threadIdx.x & 31;
    int c0 = 2 * lane;

    float aldn = g_al2d[n];
    float al = g_al2s[n] + aldn;
    float ee = al > 0.f ? al : NEG_SLOPE * al;
    float wgt = __expf(ee);
    float2 hv = *reinterpret_cast<const float2*>(&g_h2[(size_t)n * HID + c0]);
    float ax = wgt * hv.x, ay = wgt * hv.y, den = wgt;

    int beg = g_rowptr[n], end = g_rowptr[n + 1];
    for (int base = beg; base < end; base += 32) {
        int rem = end - base;
        int j = base + lane;
        int s = (lane < rem) ? g_ssrc[j] : 0;
        if (rem >= 32) {
#pragma unroll 8
            for (int t = 0; t < 32; ++t) {
                int sj = __shfl_sync(0xffffffffu, s, t);
                float a2 = g_al2s[sj] + aldn;
                float e2 = a2 > 0.f ? a2 : NEG_SLOPE * a2;
                float w2 = __expf(e2);
                float2 h2 = *reinterpret_cast<const float2*>(&g_h2[(size_t)sj * HID + c0]);
                ax += w2 * h2.x; ay += w2 * h2.y; den += w2;
            }
        } else {
            for (int t = 0; t < rem; ++t) {
                int sj = __shfl_sync(0xffffffffu, s, t);
                float a2 = g_al2s[sj] + aldn;
                float e2 = a2 > 0.f ? a2 : NEG_SLOPE * a2;
                float w2 = __expf(e2);
                float2 h2 = *reinterpret_cast<const float2*>(&g_h2[(size_t)sj * HID + c0]);
                ax += w2 * h2.x; ay += w2 * h2.y; den += w2;
            }
        }
    }
    float inv = 1.f / (den + 1e-16f);
    float vx = ax * inv + s_b2[c0];
    float vy = ay * inv + s_b2[c0 + 1];
    vx = vx > 0.f ? vx : expm1f(vx);
    vy = vy > 0.f ? vy : expm1f(vy);
    int b = batch[n];
    red_add_v2(&g_pool[b * HID + c0], vx, vy);
    if (lane == 0) red_add_f(&g_cnt[b], 1.f);
}

// ---------------- K8: classifier + log_softmax ----------------
__global__ void k_cls(const float* __restrict__ Wc, const float* __restrict__ bc,
                      float* __restrict__ out) {
    __shared__ float Ws[HID * NCLS];
    __shared__ float bs[NCLS];
    for (int i = threadIdx.x; i < HID * NCLS; i += blockDim.x) Ws[i] = Wc[i];
    if (threadIdx.x < NCLS) bs[threadIdx.x] = bc[threadIdx.x];
    __syncthreads();
    int g = threadIdx.x;
    if (g >= NG) return;
    float inv = 1.f / fmaxf(g_cnt[g], 1.f);
    float logit[NCLS];
#pragma unroll
    for (int q = 0; q < NCLS; ++q) logit[q] = bs[q];
    for (int c = 0; c < HID; ++c) {
        float pv = g_pool[g * HID + c] * inv;
#pragma unroll
        for (int q = 0; q < NCLS; ++q) logit[q] += pv * Ws[c * NCLS + q];
    }
    float m = logit[0];
#pragma unroll
    for (int q = 1; q < NCLS; ++q) m = fmaxf(m, logit[q]);
    float ssum = 0.f;
#pragma unroll
    for (int q = 0; q < NCLS; ++q) ssum += expf(logit[q] - m);
    float lse = m + logf(ssum);
#pragma unroll
    for (int q = 0; q < NCLS; ++q) out[g * NCLS + q] = logit[q] - lse;
}

// ---------------- launcher ----------------
extern "C" void kernel_launch(void* const* d_in, const int* in_sizes, int n_in,
                              void* d_out, int out_size) {
    const float* x      = (const float*)d_in[0];
    const int*   ei     = (const int*)  d_in[1];
    const int*   batch  = (const int*)  d_in[2];
    const float* W1     = (const float*)d_in[3];
    const float* a_src1 = (const float*)d_in[4];
    const float* a_dst1 = (const float*)d_in[5];
    const float* b1     = (const float*)d_in[6];
    const float* W2     = (const float*)d_in[7];
    const float* a_src2 = (const float*)d_in[8];
    const float* a_dst2 = (const float*)d_in[9];
    const float* b2     = (const float*)d_in[10];
    const float* Wc     = (const float*)d_in[11];
    const float* bc     = (const float*)d_in[12];
    float* out = (float*)d_out;
    const int* srcp = ei;
    const int* dstp = ei + N_EDGES;

    static cudaStream_t s_side = nullptr;
    static cudaEvent_t  s_fork = nullptr, s_join = nullptr;
    if (s_side == nullptr) {
        cudaStreamCreateWithFlags(&s_side, cudaStreamNonBlocking);
        cudaEventCreateWithFlags(&s_fork, cudaEventDisableTiming);
        cudaEventCreateWithFlags(&s_join, cudaEventDisableTiming);
    }

    // fork: CSR build on side stream, GEMM path on main stream (independent dataflows)
    cudaEventRecord(s_fork, 0);
    cudaStreamWaitEvent(s_side, s_fork, 0);

    k_zs<<<(N_NODES + 255) / 256, 256, 0, s_side>>>();
    k_hist<<<(N_EDGES + 255) / 256, 256, 0, s_side>>>(dstp);
    k_scan<<<1, 1024, 0, s_side>>>();
    k_scatter<<<(N_EDGES + 255) / 256, 256, 0, s_side>>>(srcp, dstp);
    cudaEventRecord(s_join, s_side);

    k_prepW<<<(HID * KPAD + 255) / 256, 256>>>(W1);
    k_gemm1_mma<<<(N_NODES + 127) / 128, 256>>>(x, a_src1, a_dst1);

    // join: edge pass needs both GEMM output and CSR
    cudaStreamWaitEvent(0, s_join, 0);

    k_edge1_csr<<<(N_NODES + 7) / 8, 256>>>(b1);
    k_layer2_mm<<<1480, 256>>>(W2, a_src2, a_dst2);
    k_edge2_csr<<<(N_NODES + 7) / 8, 256>>>(b2, batch);
    k_cls<<<1, 128>>>(Wc, bc, out);
}